// round 1
// baseline (speedup 1.0000x reference)
#include <cuda_runtime.h>
#include <math.h>

// ---------------- problem constants ----------------
#define TT      8          // frames
#define PPF     576
#define TPF     578
#define SEQ     (TT*TPF)   // 4624
#define DMODEL  768
#define VD      1024
#define NL      12
#define NH      12
#define HD      64
#define FF      3072
#define VISROWS (TT*PPF)   // 4608

// ---------------- scratch (static device globals; no allocs allowed) ----------------
__device__ float g_x  [SEQ * DMODEL];
__device__ float g_h  [SEQ * DMODEL];
__device__ float g_qkv[SEQ * 3 * DMODEL];
__device__ float g_ctx[SEQ * DMODEL];
__device__ float g_ff [SEQ * FF];
__device__ float g_vis[VISROWS * DMODEL];

// =====================================================================
// Generic fp32 GEMM: C[M,N] = act(A[M,K] @ W[N,K]^T + bias) (+ resid)
// BM=BN=128, BK=16, 256 threads, 8x8 per-thread microtile.
// N must be a multiple of 128, K a multiple of 16. M is guarded.
// MAP: remap A row m -> (m/576)*578 + (m%576) + 2 (final output gather).
// ACT: 0 = none, 1 = exact GELU.
// =====================================================================
template<int ACT, bool RESID, bool MAP>
__global__ __launch_bounds__(256)
void gemm_kernel(const float* __restrict__ A,
                 const float* __restrict__ W,
                 const float* __restrict__ bias,
                 const float* __restrict__ resid,
                 float* __restrict__ C,
                 int M, int N, int K)
{
    __shared__ float As[16][128];
    __shared__ float Bs[16][128];

    const int m0 = blockIdx.y * 128;
    const int n0 = blockIdx.x * 128;
    const int tid = threadIdx.x;
    const int tx  = tid & 15;       // 0..15 -> n
    const int ty  = tid >> 4;       // 0..15 -> m

    float acc[8][8];
#pragma unroll
    for (int i = 0; i < 8; i++)
#pragma unroll
        for (int j = 0; j < 8; j++) acc[i][j] = 0.f;

    for (int k0 = 0; k0 < K; k0 += 16) {
        // load A tile (128 rows x 16 k) and W tile, transposed into smem
#pragma unroll
        for (int it = 0; it < 2; it++) {
            int idx  = tid + it * 256;     // 0..511
            int row  = idx >> 2;           // 0..127
            int quad = idx & 3;            // 0..3 (k chunk of 4)
            // A
            float4 va = make_float4(0.f, 0.f, 0.f, 0.f);
            int m = m0 + row;
            if (m < M) {
                int am = m;
                if (MAP) { int t = m / PPF; int p = m - t * PPF; am = t * TPF + 2 + p; }
                va = *reinterpret_cast<const float4*>(&A[(size_t)am * K + k0 + quad * 4]);
            }
            As[quad * 4 + 0][row] = va.x;
            As[quad * 4 + 1][row] = va.y;
            As[quad * 4 + 2][row] = va.z;
            As[quad * 4 + 3][row] = va.w;
            // W  (N is multiple of 128 -> always in bounds)
            int n = n0 + row;
            float4 vb = *reinterpret_cast<const float4*>(&W[(size_t)n * K + k0 + quad * 4]);
            Bs[quad * 4 + 0][row] = vb.x;
            Bs[quad * 4 + 1][row] = vb.y;
            Bs[quad * 4 + 2][row] = vb.z;
            Bs[quad * 4 + 3][row] = vb.w;
        }
        __syncthreads();

#pragma unroll
        for (int kk = 0; kk < 16; kk++) {
            float a[8], b[8];
            *reinterpret_cast<float4*>(&a[0]) = *reinterpret_cast<const float4*>(&As[kk][ty * 8]);
            *reinterpret_cast<float4*>(&a[4]) = *reinterpret_cast<const float4*>(&As[kk][ty * 8 + 4]);
            *reinterpret_cast<float4*>(&b[0]) = *reinterpret_cast<const float4*>(&Bs[kk][tx * 8]);
            *reinterpret_cast<float4*>(&b[4]) = *reinterpret_cast<const float4*>(&Bs[kk][tx * 8 + 4]);
#pragma unroll
            for (int i = 0; i < 8; i++)
#pragma unroll
                for (int j = 0; j < 8; j++)
                    acc[i][j] = fmaf(a[i], b[j], acc[i][j]);
        }
        __syncthreads();
    }

    // epilogue
#pragma unroll
    for (int i = 0; i < 8; i++) {
        int m = m0 + ty * 8 + i;
        if (m >= M) continue;
#pragma unroll
        for (int j = 0; j < 8; j++) {
            int n = n0 + tx * 8 + j;
            float v = acc[i][j] + bias[n];
            if (ACT == 1) v = 0.5f * v * (1.f + erff(v * 0.70710678118654752f));
            if (RESID)    v += resid[(size_t)m * N + n];
            C[(size_t)m * N + n] = v;
        }
    }
}

// =====================================================================
// LayerNorm: one block per row, D = 768, 256 threads (3 elems each)
// =====================================================================
__device__ __forceinline__ float block_reduce_sum(float v)
{
    __shared__ float red[8];
    int lane = threadIdx.x & 31, w = threadIdx.x >> 5;
#pragma unroll
    for (int o = 16; o; o >>= 1) v += __shfl_xor_sync(0xffffffffu, v, o);
    if (!lane) red[w] = v;
    __syncthreads();
    if (w == 0) {
        v = (lane < 8) ? red[lane] : 0.f;
#pragma unroll
        for (int o = 4; o; o >>= 1) v += __shfl_xor_sync(0xffffffffu, v, o);
        if (!lane) red[0] = v;
    }
    __syncthreads();
    float r = red[0];
    __syncthreads();
    return r;
}

__global__ __launch_bounds__(256)
void ln_kernel(const float* __restrict__ x, const float* __restrict__ g,
               const float* __restrict__ b, float* __restrict__ y)
{
    const int row = blockIdx.x;
    const float* xr = x + (size_t)row * DMODEL;
    float vals[3];
    float s = 0.f;
#pragma unroll
    for (int i = 0; i < 3; i++) {
        vals[i] = xr[threadIdx.x + i * 256];
        s += vals[i];
    }
    float mu = block_reduce_sum(s) * (1.f / DMODEL);
    float vs = 0.f;
#pragma unroll
    for (int i = 0; i < 3; i++) {
        float d = vals[i] - mu;
        vs += d * d;
    }
    float var = block_reduce_sum(vs) * (1.f / DMODEL);
    float rstd = rsqrtf(var + 1e-5f);
#pragma unroll
    for (int i = 0; i < 3; i++) {
        int c = threadIdx.x + i * 256;
        y[(size_t)row * DMODEL + c] = (vals[i] - mu) * rstd * g[c] + b[c];
    }
}

// =====================================================================
// Embedding assembly
// =====================================================================
__global__ void vis_assemble(const float* __restrict__ vis,
                             const float* __restrict__ fe,
                             float* __restrict__ x)
{
    int r = blockIdx.x;            // 0..4607 (t, p)
    int t = r / PPF, p = r - t * PPF;
    int s = t * TPF + 2 + p;
    for (int d = threadIdx.x; d < DMODEL; d += blockDim.x)
        x[(size_t)s * DMODEL + d] = vis[(size_t)r * DMODEL + d] + fe[t * DMODEL + d];
}

__global__ void act_state_embed(const float* __restrict__ actions,
                                const float* __restrict__ states,
                                const float* __restrict__ aw, const float* __restrict__ ab,
                                const float* __restrict__ sw, const float* __restrict__ sb,
                                float* __restrict__ x)
{
    int t = blockIdx.x >> 1;
    int which = blockIdx.x & 1;    // 0 = action, 1 = state
    const float* inp = (which ? states : actions) + t * 7;
    const float* w   = which ? sw : aw;
    const float* bb  = which ? sb : ab;

    int f  = threadIdx.x;          // 0..383 (pair index)
    int de = 2 * f, dd = 2 * f + 1;
    float e = bb[de], o = bb[dd];
#pragma unroll
    for (int a = 0; a < 7; a++) {
        e = fmaf(inp[a], w[de * 7 + a], e);
        o = fmaf(inp[a], w[dd * 7 + a], o);
    }
    float ang = (float)t * expf(-logf(10000.f) * ((float)de / (float)DMODEL));
    float c = cosf(ang), sn = sinf(ang);
    int s = t * TPF + which;
    x[(size_t)s * DMODEL + de] = e * c - o * sn;
    x[(size_t)s * DMODEL + dd] = e * sn + o * c;
}

// =====================================================================
// Flash attention with frame-level block-causal mask.
// One block per (64-query tile, head). 256 threads, 4x4 microtile.
// qkv layout: [S, 3*768]; q at h*64, k at 768+h*64, v at 1536+h*64.
// =====================================================================
#define ATTN_SMEM ((64*64 + 3*64*65) * 4)

__global__ __launch_bounds__(256)
void attn_kernel(const float* __restrict__ qkv, float* __restrict__ ctx)
{
    extern __shared__ float sm[];
    float* Qs = sm;                 // [64][64]
    float* Ks = Qs + 64 * 64;       // [64][65]
    float* Vs = Ks + 64 * 65;       // [64][65]
    float* Ps = Vs + 64 * 65;       // [64][65]

    const int q0 = blockIdx.x * 64;
    const int h  = blockIdx.y;
    const int tid = threadIdx.x;
    const int tx = tid & 15;        // key/col group
    const int ty = tid >> 4;        // query/row group

    // load Q tile (pre-scaled)
    for (int i = tid; i < 64 * 64; i += 256) {
        int r = i >> 6, d = i & 63;
        int q = q0 + r;
        Qs[i] = (q < SEQ) ? qkv[(size_t)q * 2304 + h * 64 + d] * 0.125f : 0.f;
    }
    __syncthreads();

    float m[4], l[4], o[4][4];
#pragma unroll
    for (int i = 0; i < 4; i++) {
        m[i] = -1e30f; l[i] = 0.f;
#pragma unroll
        for (int j = 0; j < 4; j++) o[i][j] = 0.f;
    }

    int qmax = min(q0 + 63, SEQ - 1);
    int kv_end = min(SEQ, (qmax / TPF + 1) * TPF);

    int qrow[4], qframe[4];
#pragma unroll
    for (int i = 0; i < 4; i++) {
        qrow[i] = q0 + ty * 4 + i;
        qframe[i] = qrow[i] / TPF;
    }

    for (int k0 = 0; k0 < kv_end; k0 += 64) {
        // load K, V tiles
        for (int i = tid; i < 64 * 64; i += 256) {
            int r = i >> 6, d = i & 63;
            int k = k0 + r;
            float kv = 0.f, vv = 0.f;
            if (k < SEQ) {
                kv = qkv[(size_t)k * 2304 + 768  + h * 64 + d];
                vv = qkv[(size_t)k * 2304 + 1536 + h * 64 + d];
            }
            Ks[r * 65 + d] = kv;
            Vs[r * 65 + d] = vv;
        }
        __syncthreads();

        // S = Q @ K^T   (4x4 per thread)
        float s4[4][4];
#pragma unroll
        for (int i = 0; i < 4; i++)
#pragma unroll
            for (int j = 0; j < 4; j++) s4[i][j] = 0.f;

        for (int d = 0; d < 64; d++) {
            float qv[4], kv[4];
#pragma unroll
            for (int i = 0; i < 4; i++) qv[i] = Qs[(ty * 4 + i) * 64 + d];
#pragma unroll
            for (int j = 0; j < 4; j++) kv[j] = Ks[(tx * 4 + j) * 65 + d];
#pragma unroll
            for (int i = 0; i < 4; i++)
#pragma unroll
                for (int j = 0; j < 4; j++)
                    s4[i][j] = fmaf(qv[i], kv[j], s4[i][j]);
        }

        // mask (frame-causal)
#pragma unroll
        for (int j = 0; j < 4; j++) {
            int k = k0 + tx * 4 + j;
            int fk = k / TPF;
            bool koob = (k >= SEQ);
#pragma unroll
            for (int i = 0; i < 4; i++)
                if (koob || fk > qframe[i]) s4[i][j] = -1e30f;
        }

        // online softmax (row reductions across the 16-lane tx group)
#pragma unroll
        for (int i = 0; i < 4; i++) {
            float rmax = fmaxf(fmaxf(s4[i][0], s4[i][1]), fmaxf(s4[i][2], s4[i][3]));
#pragma unroll
            for (int off = 1; off < 16; off <<= 1)
                rmax = fmaxf(rmax, __shfl_xor_sync(0xffffffffu, rmax, off));
            float mnew = fmaxf(m[i], rmax);
            float csc = expf(m[i] - mnew);
            m[i] = mnew;
            float rs = 0.f;
#pragma unroll
            for (int j = 0; j < 4; j++) {
                s4[i][j] = expf(s4[i][j] - mnew);
                rs += s4[i][j];
            }
#pragma unroll
            for (int off = 1; off < 16; off <<= 1)
                rs += __shfl_xor_sync(0xffffffffu, rs, off);
            l[i] = l[i] * csc + rs;
#pragma unroll
            for (int j = 0; j < 4; j++) o[i][j] *= csc;
#pragma unroll
            for (int j = 0; j < 4; j++)
                Ps[(ty * 4 + i) * 65 + tx * 4 + j] = s4[i][j];
        }
        __syncthreads();

        // O += P @ V
        for (int kk = 0; kk < 64; kk++) {
            float pv[4], vv[4];
#pragma unroll
            for (int i = 0; i < 4; i++) pv[i] = Ps[(ty * 4 + i) * 65 + kk];
#pragma unroll
            for (int j = 0; j < 4; j++) vv[j] = Vs[kk * 65 + tx * 4 + j];
#pragma unroll
            for (int i = 0; i < 4; i++)
#pragma unroll
                for (int j = 0; j < 4; j++)
                    o[i][j] = fmaf(pv[i], vv[j], o[i][j]);
        }
        __syncthreads();
    }

    // write ctx
#pragma unroll
    for (int i = 0; i < 4; i++) {
        int q = qrow[i];
        if (q >= SEQ) continue;
        float inv = 1.f / l[i];
#pragma unroll
        for (int j = 0; j < 4; j++)
            ctx[(size_t)q * DMODEL + h * 64 + tx * 4 + j] = o[i][j] * inv;
    }
}

// =====================================================================
// host launcher
// =====================================================================
extern "C" void kernel_launch(void* const* d_in, const int* in_sizes, int n_in,
                              void* d_out, int out_size)
{
    const float* visual_tokens  = (const float*)d_in[0];
    const float* actions        = (const float*)d_in[1];
    const float* states         = (const float*)d_in[2];
    const float* visual_proj_w  = (const float*)d_in[3];
    const float* visual_proj_b  = (const float*)d_in[4];
    const float* action_proj_w  = (const float*)d_in[5];
    const float* action_proj_b  = (const float*)d_in[6];
    const float* state_proj_w   = (const float*)d_in[7];
    const float* state_proj_b   = (const float*)d_in[8];
    const float* frame_embed    = (const float*)d_in[9];
    const float* qkv_w          = (const float*)d_in[10];
    const float* qkv_b          = (const float*)d_in[11];
    const float* attn_out_w     = (const float*)d_in[12];
    const float* attn_out_b     = (const float*)d_in[13];
    const float* ln1_g          = (const float*)d_in[14];
    const float* ln1_b          = (const float*)d_in[15];
    const float* ff1_w          = (const float*)d_in[16];
    const float* ff1_b          = (const float*)d_in[17];
    const float* ff2_w          = (const float*)d_in[18];
    const float* ff2_b          = (const float*)d_in[19];
    const float* ln2_g          = (const float*)d_in[20];
    const float* ln2_b          = (const float*)d_in[21];
    const float* out_norm_g     = (const float*)d_in[22];
    const float* out_norm_b     = (const float*)d_in[23];
    const float* output_proj_w  = (const float*)d_in[24];
    const float* output_proj_b  = (const float*)d_in[25];

    float *x, *h, *qkvb, *ctx, *ff, *vis;
    cudaGetSymbolAddress((void**)&x,    g_x);
    cudaGetSymbolAddress((void**)&h,    g_h);
    cudaGetSymbolAddress((void**)&qkvb, g_qkv);
    cudaGetSymbolAddress((void**)&ctx,  g_ctx);
    cudaGetSymbolAddress((void**)&ff,   g_ff);
    cudaGetSymbolAddress((void**)&vis,  g_vis);

    cudaFuncSetAttribute(attn_kernel, cudaFuncAttributeMaxDynamicSharedMemorySize, ATTN_SMEM);

    const int MT  = (SEQ + 127) / 128;      // 37 m-tiles for S=4624
    const int MTV = VISROWS / 128;          // 36 m-tiles for 4608

    // ---- embeddings ----
    gemm_kernel<0,false,false><<<dim3(DMODEL/128, MTV), 256>>>(
        visual_tokens, visual_proj_w, visual_proj_b, nullptr, vis,
        VISROWS, DMODEL, VD);
    vis_assemble<<<VISROWS, 256>>>(vis, frame_embed, x);
    act_state_embed<<<2*TT, 384>>>(actions, states,
        action_proj_w, action_proj_b, state_proj_w, state_proj_b, x);

    // ---- transformer layers ----
    for (int i = 0; i < NL; i++) {
        ln_kernel<<<SEQ, 256>>>(x, ln1_g + i*DMODEL, ln1_b + i*DMODEL, h);
        gemm_kernel<0,false,false><<<dim3(3*DMODEL/128, MT), 256>>>(
            h, qkv_w + (size_t)i*3*DMODEL*DMODEL, qkv_b + (size_t)i*3*DMODEL,
            nullptr, qkvb, SEQ, 3*DMODEL, DMODEL);
        attn_kernel<<<dim3((SEQ + 63)/64, NH), 256, ATTN_SMEM>>>(qkvb, ctx);
        gemm_kernel<0,true,false><<<dim3(DMODEL/128, MT), 256>>>(
            ctx, attn_out_w + (size_t)i*DMODEL*DMODEL, attn_out_b + (size_t)i*DMODEL,
            x, x, SEQ, DMODEL, DMODEL);
        ln_kernel<<<SEQ, 256>>>(x, ln2_g + i*DMODEL, ln2_b + i*DMODEL, h);
        gemm_kernel<1,false,false><<<dim3(FF/128, MT), 256>>>(
            h, ff1_w + (size_t)i*FF*DMODEL, ff1_b + (size_t)i*FF,
            nullptr, ff, SEQ, FF, DMODEL);
        gemm_kernel<0,true,false><<<dim3(DMODEL/128, MT), 256>>>(
            ff, ff2_w + (size_t)i*DMODEL*FF, ff2_b + (size_t)i*DMODEL,
            x, x, SEQ, DMODEL, FF);
    }

    // ---- output head ----
    ln_kernel<<<SEQ, 256>>>(x, out_norm_g, out_norm_b, h);
    gemm_kernel<0,false,true><<<dim3(VD/128, MTV), 256>>>(
        h, output_proj_w, output_proj_b, nullptr, (float*)d_out,
        VISROWS, VD, DMODEL);
}

// round 2
// speedup vs baseline: 3.1231x; 3.1231x over previous
#include <cuda_runtime.h>
#include <math.h>
#include <stdint.h>

// ---------------- problem constants ----------------
#define TT      8
#define PPF     576
#define TPF     578
#define SEQ     (TT*TPF)   // 4624
#define DMODEL  768
#define VD      1024
#define NL      12
#define NH      12
#define FF      3072
#define VISROWS (TT*PPF)   // 4608

// ---------------- scratch ----------------
__device__ float g_x  [SEQ * DMODEL];
__device__ float g_h  [SEQ * DMODEL];
__device__ float g_qkv[SEQ * 3 * DMODEL];
__device__ float g_ctx[SEQ * DMODEL];
__device__ float g_ff [SEQ * FF];
__device__ float g_vis[VISROWS * DMODEL];

// ---------------- tf32 helpers ----------------
__device__ __forceinline__ uint32_t f2tf(float x) {
    uint32_t r; asm("cvt.rna.tf32.f32 %0, %1;" : "=r"(r) : "f"(x)); return r;
}
__device__ __forceinline__ float f2tff(float x) { return __uint_as_float(f2tf(x)); }
__device__ __forceinline__ uint32_t fu(float x) { return __float_as_uint(x); }

__device__ __forceinline__ void mma8(float* d, const uint32_t* a, uint32_t b0, uint32_t b1) {
    asm volatile(
        "mma.sync.aligned.m16n8k8.row.col.f32.tf32.tf32.f32 "
        "{%0,%1,%2,%3},{%4,%5,%6,%7},{%8,%9},{%0,%1,%2,%3};"
        : "+f"(d[0]), "+f"(d[1]), "+f"(d[2]), "+f"(d[3])
        : "r"(a[0]), "r"(a[1]), "r"(a[2]), "r"(a[3]), "r"(b0), "r"(b1));
}

// =====================================================================
// TF32 tensor-core GEMM: C[M,N] = act(A[M,K] @ W[N,K]^T + bias) (+resid)
// BM=BN=128, BK=32. 256 threads = 8 warps (2m x 4n), warp tile 64x32.
// smem tiles padded to stride 36 (== 4 mod 32 -> conflict-free frags).
// Double-buffered with register staging. tf32 conversion producer-side.
// =====================================================================
#define BK   32
#define LDT  36
#define GEMM_SMEM (2 * 2 * 128 * LDT * 4)   // 73728 bytes

template<int ACT, bool RESID, bool MAP>
__global__ __launch_bounds__(256)
void gemm_tc(const float* __restrict__ A, const float* __restrict__ W,
             const float* __restrict__ bias, const float* __restrict__ resid,
             float* __restrict__ C, int M, int N, int K)
{
    extern __shared__ float sm[];
    const int m0 = blockIdx.y * 128, n0 = blockIdx.x * 128;
    const int tid = threadIdx.x, lane = tid & 31, warp = tid >> 5;
    const int wm = (warp >> 2) * 64, wn = (warp & 3) * 32;
    const int g = lane >> 2, t = lane & 3;

    float acc[4][4][4];
#pragma unroll
    for (int a = 0; a < 4; a++)
#pragma unroll
        for (int b = 0; b < 4; b++)
#pragma unroll
            for (int c = 0; c < 4; c++) acc[a][b][c] = 0.f;

    float4 sa[4], sb[4];

    auto loadg = [&](int c) {
        int kb = c * BK;
#pragma unroll
        for (int i = 0; i < 4; i++) {
            int idx = tid + i * 256; int row = idx >> 3; int c4 = idx & 7;
            int m = m0 + row;
            float4 v = make_float4(0.f, 0.f, 0.f, 0.f);
            if (m < M) {
                int am = m;
                if (MAP) { int tt = m / PPF; am = tt * TPF + 2 + (m - tt * PPF); }
                v = *reinterpret_cast<const float4*>(A + (size_t)am * K + kb + c4 * 4);
            }
            sa[i] = v;
            sb[i] = *reinterpret_cast<const float4*>(W + (size_t)(n0 + row) * K + kb + c4 * 4);
        }
    };

    auto stores = [&](int buf) {
        float* As = sm + buf * (2 * 128 * LDT);
        float* Bs = As + 128 * LDT;
#pragma unroll
        for (int i = 0; i < 4; i++) {
            int idx = tid + i * 256; int row = idx >> 3; int c4 = idx & 7;
            float4 va = sa[i];
            va.x = f2tff(va.x); va.y = f2tff(va.y); va.z = f2tff(va.z); va.w = f2tff(va.w);
            *reinterpret_cast<float4*>(As + row * LDT + c4 * 4) = va;
            float4 vb = sb[i];
            vb.x = f2tff(vb.x); vb.y = f2tff(vb.y); vb.z = f2tff(vb.z); vb.w = f2tff(vb.w);
            *reinterpret_cast<float4*>(Bs + row * LDT + c4 * 4) = vb;
        }
    };

    auto comp = [&](int buf) {
        const float* As = sm + buf * (2 * 128 * LDT);
        const float* Bs = As + 128 * LDT;
#pragma unroll
        for (int ks = 0; ks < 4; ks++) {
            int kb = ks * 8;
            uint32_t af[4][4];
#pragma unroll
            for (int mt = 0; mt < 4; mt++) {
                const float* p = As + (wm + mt * 16 + g) * LDT + kb + t;
                af[mt][0] = fu(p[0]);
                af[mt][1] = fu(p[8 * LDT]);
                af[mt][2] = fu(p[4]);
                af[mt][3] = fu(p[8 * LDT + 4]);
            }
#pragma unroll
            for (int nt = 0; nt < 4; nt++) {
                const float* q = Bs + (wn + nt * 8 + g) * LDT + kb + t;
                uint32_t b0 = fu(q[0]), b1 = fu(q[4]);
#pragma unroll
                for (int mt = 0; mt < 4; mt++) mma8(acc[mt][nt], af[mt], b0, b1);
            }
        }
    };

    const int NC = K / BK;
    loadg(0); stores(0); __syncthreads();
    for (int c = 0; c < NC; c++) {
        if (c + 1 < NC) loadg(c + 1);
        comp(c & 1);
        if (c + 1 < NC) stores((c + 1) & 1);
        __syncthreads();
    }

    // epilogue: c-frag rows g,g+8; cols 2t,2t+1
#pragma unroll
    for (int mt = 0; mt < 4; mt++) {
#pragma unroll
        for (int r = 0; r < 2; r++) {
            int m = m0 + wm + mt * 16 + g + r * 8;
            if (m >= M) continue;
#pragma unroll
            for (int nt = 0; nt < 4; nt++) {
                int n = n0 + wn + nt * 8 + t * 2;
                float v0 = acc[mt][nt][r * 2 + 0] + bias[n];
                float v1 = acc[mt][nt][r * 2 + 1] + bias[n + 1];
                if (ACT == 1) {
                    v0 = 0.5f * v0 * (1.f + erff(v0 * 0.70710678118654752f));
                    v1 = 0.5f * v1 * (1.f + erff(v1 * 0.70710678118654752f));
                }
                if (RESID) {
                    const float* rr = resid + (size_t)m * N + n;
                    v0 += rr[0]; v1 += rr[1];
                }
                *reinterpret_cast<float2*>(C + (size_t)m * N + n) = make_float2(v0, v1);
            }
        }
    }
}

// =====================================================================
// TF32 flash attention, frame block-causal mask.
// Block: 64 queries x 1 head, 128 threads (4 warps, 16 q-rows each).
// =====================================================================
#define QLD 68
#define VLD 72
#define ATTN_SMEM ((64 * QLD * 3 + 64 * VLD) * 4)   // 70656 bytes

__global__ __launch_bounds__(128)
void attn_tc(const float* __restrict__ qkv, float* __restrict__ ctx)
{
    extern __shared__ float sm[];
    float* Qs = sm;                 // [64][QLD]
    float* Ks = Qs + 64 * QLD;      // [64][QLD]
    float* Vs = Ks + 64 * QLD;      // [64][VLD]  (keys x d)
    float* Ps = Vs + 64 * VLD;      // [64][QLD]

    const int q0 = blockIdx.x * 64, h = blockIdx.y;
    const int tid = threadIdx.x, lane = tid & 31, warp = tid >> 5;
    const int g = lane >> 2, t = lane & 3;
    const int wq = warp * 16;

    // load Q (scaled by 1/8, tf32)
    for (int idx = tid; idx < 64 * 16; idx += 128) {
        int row = idx >> 4, c4 = idx & 15;
        int q = q0 + row;
        float4 v = make_float4(0.f, 0.f, 0.f, 0.f);
        if (q < SEQ) v = *reinterpret_cast<const float4*>(qkv + (size_t)q * 2304 + h * 64 + c4 * 4);
        v.x = f2tff(v.x * 0.125f); v.y = f2tff(v.y * 0.125f);
        v.z = f2tff(v.z * 0.125f); v.w = f2tff(v.w * 0.125f);
        *reinterpret_cast<float4*>(Qs + row * QLD + c4 * 4) = v;
    }

    float o[8][4];
#pragma unroll
    for (int a = 0; a < 8; a++)
#pragma unroll
        for (int b = 0; b < 4; b++) o[a][b] = 0.f;
    float mrow[2] = {-1e30f, -1e30f}, lrow[2] = {0.f, 0.f};

    int qmax = min(q0 + 63, SEQ - 1);
    int kv_end = min(SEQ, (qmax / TPF + 1) * TPF);

    int qrow0 = q0 + wq + g;
    int qlim0 = (qrow0 / TPF + 1) * TPF;
    int qlim1 = ((qrow0 + 8) / TPF + 1) * TPF;
    int qlim_w = ((q0 + wq) / TPF + 1) * TPF;

    for (int k0 = 0; k0 < kv_end; k0 += 64) {
        __syncthreads();
        // load K, V tiles (tf32)
        for (int idx = tid; idx < 64 * 16; idx += 128) {
            int row = idx >> 4, c4 = idx & 15;
            int k = k0 + row;
            float4 kv4 = make_float4(0.f, 0.f, 0.f, 0.f);
            float4 vv4 = make_float4(0.f, 0.f, 0.f, 0.f);
            if (k < SEQ) {
                kv4 = *reinterpret_cast<const float4*>(qkv + (size_t)k * 2304 + 768  + h * 64 + c4 * 4);
                vv4 = *reinterpret_cast<const float4*>(qkv + (size_t)k * 2304 + 1536 + h * 64 + c4 * 4);
            }
            kv4.x = f2tff(kv4.x); kv4.y = f2tff(kv4.y); kv4.z = f2tff(kv4.z); kv4.w = f2tff(kv4.w);
            vv4.x = f2tff(vv4.x); vv4.y = f2tff(vv4.y); vv4.z = f2tff(vv4.z); vv4.w = f2tff(vv4.w);
            *reinterpret_cast<float4*>(Ks + row * QLD + c4 * 4) = kv4;
            *reinterpret_cast<float4*>(Vs + row * VLD + c4 * 4) = vv4;
        }
        __syncthreads();

        // S = Q @ K^T  (per warp: 16 q-rows x 64 keys)
        float sacc[8][4];
#pragma unroll
        for (int a = 0; a < 8; a++)
#pragma unroll
            for (int b = 0; b < 4; b++) sacc[a][b] = 0.f;

#pragma unroll
        for (int ks = 0; ks < 8; ks++) {
            uint32_t af[4];
            const float* p = Qs + (wq + g) * QLD + ks * 8 + t;
            af[0] = fu(p[0]); af[1] = fu(p[8 * QLD]);
            af[2] = fu(p[4]); af[3] = fu(p[8 * QLD + 4]);
#pragma unroll
            for (int nt = 0; nt < 8; nt++) {
                const float* q = Ks + (nt * 8 + g) * QLD + ks * 8 + t;
                mma8(sacc[nt], af, fu(q[0]), fu(q[4]));
            }
        }

        // frame-causal mask (only on boundary tiles)
        if (k0 + 63 >= qlim_w) {
#pragma unroll
            for (int nt = 0; nt < 8; nt++) {
                int kc = k0 + nt * 8 + t * 2;
                if (kc     >= qlim0) sacc[nt][0] = -1e30f;
                if (kc + 1 >= qlim0) sacc[nt][1] = -1e30f;
                if (kc     >= qlim1) sacc[nt][2] = -1e30f;
                if (kc + 1 >= qlim1) sacc[nt][3] = -1e30f;
            }
        }

        // online softmax (rows g, g+8)
#pragma unroll
        for (int r = 0; r < 2; r++) {
            float mx = -1e30f;
#pragma unroll
            for (int nt = 0; nt < 8; nt++)
                mx = fmaxf(mx, fmaxf(sacc[nt][r * 2], sacc[nt][r * 2 + 1]));
            mx = fmaxf(mx, __shfl_xor_sync(0xffffffffu, mx, 1));
            mx = fmaxf(mx, __shfl_xor_sync(0xffffffffu, mx, 2));
            float mnew = fmaxf(mrow[r], mx);
            float scale = __expf(mrow[r] - mnew);
            mrow[r] = mnew;
            float rs = 0.f;
#pragma unroll
            for (int nt = 0; nt < 8; nt++) {
                float p0 = __expf(sacc[nt][r * 2]     - mnew);
                float p1 = __expf(sacc[nt][r * 2 + 1] - mnew);
                sacc[nt][r * 2] = p0; sacc[nt][r * 2 + 1] = p1;
                rs += p0 + p1;
            }
            rs += __shfl_xor_sync(0xffffffffu, rs, 1);
            rs += __shfl_xor_sync(0xffffffffu, rs, 2);
            lrow[r] = lrow[r] * scale + rs;
#pragma unroll
            for (int nt = 0; nt < 8; nt++) { o[nt][r * 2] *= scale; o[nt][r * 2 + 1] *= scale; }
#pragma unroll
            for (int nt = 0; nt < 8; nt++) {
                float* dst = Ps + (wq + g + r * 8) * QLD + nt * 8 + t * 2;
                dst[0] = f2tff(sacc[nt][r * 2]);
                dst[1] = f2tff(sacc[nt][r * 2 + 1]);
            }
        }
        __syncwarp();

        // O += P @ V
#pragma unroll
        for (int ks = 0; ks < 8; ks++) {
            uint32_t af[4];
            const float* p = Ps + (wq + g) * QLD + ks * 8 + t;
            af[0] = fu(p[0]); af[1] = fu(p[8 * QLD]);
            af[2] = fu(p[4]); af[3] = fu(p[8 * QLD + 4]);
#pragma unroll
            for (int nt = 0; nt < 8; nt++) {
                const float* q = Vs + (ks * 8 + t) * VLD + nt * 8 + g;
                mma8(o[nt], af, fu(q[0]), fu(q[4 * VLD]));
            }
        }
    }

    // write ctx
#pragma unroll
    for (int r = 0; r < 2; r++) {
        int qq = q0 + wq + g + r * 8;
        if (qq >= SEQ) continue;
        float inv = 1.f / lrow[r];
#pragma unroll
        for (int nt = 0; nt < 8; nt++) {
            float* dst = ctx + (size_t)qq * DMODEL + h * 64 + nt * 8 + t * 2;
            dst[0] = o[nt][r * 2] * inv;
            dst[1] = o[nt][r * 2 + 1] * inv;
        }
    }
}

// =====================================================================
// LayerNorm + embedding kernels (unchanged from R1)
// =====================================================================
__device__ __forceinline__ float block_reduce_sum(float v)
{
    __shared__ float red[8];
    int lane = threadIdx.x & 31, w = threadIdx.x >> 5;
#pragma unroll
    for (int o = 16; o; o >>= 1) v += __shfl_xor_sync(0xffffffffu, v, o);
    if (!lane) red[w] = v;
    __syncthreads();
    if (w == 0) {
        v = (lane < 8) ? red[lane] : 0.f;
#pragma unroll
        for (int o = 4; o; o >>= 1) v += __shfl_xor_sync(0xffffffffu, v, o);
        if (!lane) red[0] = v;
    }
    __syncthreads();
    float r = red[0];
    __syncthreads();
    return r;
}

__global__ __launch_bounds__(256)
void ln_kernel(const float* __restrict__ x, const float* __restrict__ g,
               const float* __restrict__ b, float* __restrict__ y)
{
    const int row = blockIdx.x;
    const float* xr = x + (size_t)row * DMODEL;
    float vals[3];
    float s = 0.f;
#pragma unroll
    for (int i = 0; i < 3; i++) { vals[i] = xr[threadIdx.x + i * 256]; s += vals[i]; }
    float mu = block_reduce_sum(s) * (1.f / DMODEL);
    float vs = 0.f;
#pragma unroll
    for (int i = 0; i < 3; i++) { float d = vals[i] - mu; vs += d * d; }
    float var = block_reduce_sum(vs) * (1.f / DMODEL);
    float rstd = rsqrtf(var + 1e-5f);
#pragma unroll
    for (int i = 0; i < 3; i++) {
        int c = threadIdx.x + i * 256;
        y[(size_t)row * DMODEL + c] = (vals[i] - mu) * rstd * g[c] + b[c];
    }
}

__global__ void vis_assemble(const float* __restrict__ vis,
                             const float* __restrict__ fe,
                             float* __restrict__ x)
{
    int r = blockIdx.x;
    int t = r / PPF, p = r - t * PPF;
    int s = t * TPF + 2 + p;
    for (int d = threadIdx.x; d < DMODEL; d += blockDim.x)
        x[(size_t)s * DMODEL + d] = vis[(size_t)r * DMODEL + d] + fe[t * DMODEL + d];
}

__global__ void act_state_embed(const float* __restrict__ actions,
                                const float* __restrict__ states,
                                const float* __restrict__ aw, const float* __restrict__ ab,
                                const float* __restrict__ sw, const float* __restrict__ sb,
                                float* __restrict__ x)
{
    int t = blockIdx.x >> 1;
    int which = blockIdx.x & 1;
    const float* inp = (which ? states : actions) + t * 7;
    const float* w   = which ? sw : aw;
    const float* bb  = which ? sb : ab;

    int f  = threadIdx.x;
    int de = 2 * f, dd = 2 * f + 1;
    float e = bb[de], o = bb[dd];
#pragma unroll
    for (int a = 0; a < 7; a++) {
        e = fmaf(inp[a], w[de * 7 + a], e);
        o = fmaf(inp[a], w[dd * 7 + a], o);
    }
    float ang = (float)t * expf(-logf(10000.f) * ((float)de / (float)DMODEL));
    float c = cosf(ang), sn = sinf(ang);
    int s = t * TPF + which;
    x[(size_t)s * DMODEL + de] = e * c - o * sn;
    x[(size_t)s * DMODEL + dd] = e * sn + o * c;
}

// =====================================================================
// host launcher
// =====================================================================
extern "C" void kernel_launch(void* const* d_in, const int* in_sizes, int n_in,
                              void* d_out, int out_size)
{
    const float* visual_tokens  = (const float*)d_in[0];
    const float* actions        = (const float*)d_in[1];
    const float* states         = (const float*)d_in[2];
    const float* visual_proj_w  = (const float*)d_in[3];
    const float* visual_proj_b  = (const float*)d_in[4];
    const float* action_proj_w  = (const float*)d_in[5];
    const float* action_proj_b  = (const float*)d_in[6];
    const float* state_proj_w   = (const float*)d_in[7];
    const float* state_proj_b   = (const float*)d_in[8];
    const float* frame_embed    = (const float*)d_in[9];
    const float* qkv_w          = (const float*)d_in[10];
    const float* qkv_b          = (const float*)d_in[11];
    const float* attn_out_w     = (const float*)d_in[12];
    const float* attn_out_b     = (const float*)d_in[13];
    const float* ln1_g          = (const float*)d_in[14];
    const float* ln1_b          = (const float*)d_in[15];
    const float* ff1_w          = (const float*)d_in[16];
    const float* ff1_b          = (const float*)d_in[17];
    const float* ff2_w          = (const float*)d_in[18];
    const float* ff2_b          = (const float*)d_in[19];
    const float* ln2_g          = (const float*)d_in[20];
    const float* ln2_b          = (const float*)d_in[21];
    const float* out_norm_g     = (const float*)d_in[22];
    const float* out_norm_b     = (const float*)d_in[23];
    const float* output_proj_w  = (const float*)d_in[24];
    const float* output_proj_b  = (const float*)d_in[25];

    float *x, *h, *qkvb, *ctx, *ff, *vis;
    cudaGetSymbolAddress((void**)&x,    g_x);
    cudaGetSymbolAddress((void**)&h,    g_h);
    cudaGetSymbolAddress((void**)&qkvb, g_qkv);
    cudaGetSymbolAddress((void**)&ctx,  g_ctx);
    cudaGetSymbolAddress((void**)&ff,   g_ff);
    cudaGetSymbolAddress((void**)&vis,  g_vis);

    cudaFuncSetAttribute(gemm_tc<0,false,false>, cudaFuncAttributeMaxDynamicSharedMemorySize, GEMM_SMEM);
    cudaFuncSetAttribute(gemm_tc<0,true,false>,  cudaFuncAttributeMaxDynamicSharedMemorySize, GEMM_SMEM);
    cudaFuncSetAttribute(gemm_tc<1,false,false>, cudaFuncAttributeMaxDynamicSharedMemorySize, GEMM_SMEM);
    cudaFuncSetAttribute(gemm_tc<0,false,true>,  cudaFuncAttributeMaxDynamicSharedMemorySize, GEMM_SMEM);
    cudaFuncSetAttribute(attn_tc, cudaFuncAttributeMaxDynamicSharedMemorySize, ATTN_SMEM);

    const int MT  = (SEQ + 127) / 128;   // 37
    const int MTV = VISROWS / 128;       // 36

    // ---- embeddings ----
    gemm_tc<0,false,false><<<dim3(DMODEL/128, MTV), 256, GEMM_SMEM>>>(
        visual_tokens, visual_proj_w, visual_proj_b, nullptr, vis,
        VISROWS, DMODEL, VD);
    vis_assemble<<<VISROWS, 256>>>(vis, frame_embed, x);
    act_state_embed<<<2*TT, 384>>>(actions, states,
        action_proj_w, action_proj_b, state_proj_w, state_proj_b, x);

    // ---- transformer layers ----
    for (int i = 0; i < NL; i++) {
        ln_kernel<<<SEQ, 256>>>(x, ln1_g + i*DMODEL, ln1_b + i*DMODEL, h);
        gemm_tc<0,false,false><<<dim3(3*DMODEL/128, MT), 256, GEMM_SMEM>>>(
            h, qkv_w + (size_t)i*3*DMODEL*DMODEL, qkv_b + (size_t)i*3*DMODEL,
            nullptr, qkvb, SEQ, 3*DMODEL, DMODEL);
        attn_tc<<<dim3((SEQ + 63)/64, NH), 128, ATTN_SMEM>>>(qkvb, ctx);
        gemm_tc<0,true,false><<<dim3(DMODEL/128, MT), 256, GEMM_SMEM>>>(
            ctx, attn_out_w + (size_t)i*DMODEL*DMODEL, attn_out_b + (size_t)i*DMODEL,
            x, x, SEQ, DMODEL, DMODEL);
        ln_kernel<<<SEQ, 256>>>(x, ln2_g + i*DMODEL, ln2_b + i*DMODEL, h);
        gemm_tc<1,false,false><<<dim3(FF/128, MT), 256, GEMM_SMEM>>>(
            h, ff1_w + (size_t)i*FF*DMODEL, ff1_b + (size_t)i*FF,
            nullptr, ff, SEQ, FF, DMODEL);
        gemm_tc<0,true,false><<<dim3(DMODEL/128, MT), 256, GEMM_SMEM>>>(
            ff, ff2_w + (size_t)i*DMODEL*FF, ff2_b + (size_t)i*DMODEL,
            x, x, SEQ, DMODEL, FF);
    }

    // ---- output head ----
    ln_kernel<<<SEQ, 256>>>(x, out_norm_g, out_norm_b, h);
    gemm_tc<0,false,true><<<dim3(VD/128, MTV), 256, GEMM_SMEM>>>(
        h, output_proj_w, output_proj_b, nullptr, (float*)d_out,
        VISROWS, VD, DMODEL);
}

// round 3
// speedup vs baseline: 3.9142x; 1.2533x over previous
#include <cuda_runtime.h>
#include <math.h>
#include <stdint.h>

// ---------------- problem constants ----------------
#define TT      8
#define PPF     576
#define TPF     578
#define SEQ     (TT*TPF)   // 4624
#define DMODEL  768
#define VD      1024
#define NL      12
#define NH      12
#define FF      3072
#define VISROWS (TT*PPF)   // 4608

// ---------------- scratch ----------------
__device__ float g_x  [SEQ * DMODEL];
__device__ float g_h  [SEQ * DMODEL];
__device__ float g_qkv[SEQ * 3 * DMODEL];
__device__ float g_ctx[SEQ * DMODEL];
__device__ float g_ff [SEQ * FF];
// pre-rounded (tf32) copies of weights / inputs
__device__ float g_vt  [VISROWS * VD];
__device__ float g_wvp [DMODEL * VD];
__device__ float g_wqkv[NL * 3 * DMODEL * DMODEL];
__device__ float g_wao [NL * DMODEL * DMODEL];
__device__ float g_wff1[NL * FF * DMODEL];
__device__ float g_wff2[NL * DMODEL * FF];
__device__ float g_wop [VD * DMODEL];

// ---------------- helpers ----------------
__device__ __forceinline__ uint32_t f2tf(float x) {
    uint32_t r; asm("cvt.rna.tf32.f32 %0, %1;" : "=r"(r) : "f"(x)); return r;
}
__device__ __forceinline__ float f2tff(float x) { return __uint_as_float(f2tf(x)); }
__device__ __forceinline__ uint32_t fu(float x) { return __float_as_uint(x); }

__device__ __forceinline__ void mma8(float* d, const uint32_t* a, uint32_t b0, uint32_t b1) {
    asm volatile(
        "mma.sync.aligned.m16n8k8.row.col.f32.tf32.tf32.f32 "
        "{%0,%1,%2,%3},{%4,%5,%6,%7},{%8,%9},{%0,%1,%2,%3};"
        : "+f"(d[0]), "+f"(d[1]), "+f"(d[2]), "+f"(d[3])
        : "r"(a[0]), "r"(a[1]), "r"(a[2]), "r"(a[3]), "r"(b0), "r"(b1));
}

__device__ __forceinline__ uint32_t smem_u32(const void* p) {
    return (uint32_t)__cvta_generic_to_shared(p);
}
__device__ __forceinline__ void cpa16(uint32_t dst, const void* src, bool v) {
    asm volatile("cp.async.cg.shared.global [%0], [%1], 16, %2;"
                 :: "r"(dst), "l"(src), "r"(v ? 16u : 0u));
}
__device__ __forceinline__ void cpa_commit() { asm volatile("cp.async.commit_group;"); }
template<int N> __device__ __forceinline__ void cpa_wait() {
    asm volatile("cp.async.wait_group %0;" :: "n"(N));
}

// ---------------- tf32 rounding prepass ----------------
__global__ void round_tf32_k(const float* __restrict__ in, float* __restrict__ out, int n4)
{
    int i = blockIdx.x * blockDim.x + threadIdx.x;
    if (i < n4) {
        float4 v = reinterpret_cast<const float4*>(in)[i];
        v.x = f2tff(v.x); v.y = f2tff(v.y); v.z = f2tff(v.z); v.w = f2tff(v.w);
        reinterpret_cast<float4*>(out)[i] = v;
    }
}

// =====================================================================
// TF32 tensor-core GEMM, cp.async 3-stage: C = act(A @ W^T + bias)
// A and W must be pre-rounded to tf32. BM=BN=128, BK=32.
// 256 threads = 8 warps (2m x 4n), warp tile 64x32.
// =====================================================================
#define BK   32
#define LDT  36
#define STG  3
#define GEMM_SMEM (STG * 2 * 128 * LDT * 4)   // 110592 bytes

template<int ACT, bool RESID, bool MAPIN, bool FE, bool ROUND>
__global__ __launch_bounds__(256, 2)
void gemm_tc(const float* __restrict__ A, const float* __restrict__ W,
             const float* __restrict__ bias, const float* __restrict__ resid,
             const float* __restrict__ fe, float* __restrict__ C,
             int M, int N, int K)
{
    extern __shared__ float sm[];
    const int m0 = blockIdx.y * 128, n0 = blockIdx.x * 128;
    const int tid = threadIdx.x, lane = tid & 31, warp = tid >> 5;
    const int wm = (warp >> 2) * 64, wn = (warp & 3) * 32;
    const int g = lane >> 2, t = lane & 3;

    // load assignment: 4 A-chunks + 4 B-chunks (16B each) per thread per stage
    int soff[4]; const float* asrc[4]; const float* bsrc[4]; bool aval[4];
#pragma unroll
    for (int i = 0; i < 4; i++) {
        int id = tid + i * 256; int row = id >> 3; int c4 = id & 7;
        int m = m0 + row;
        bool v = m < M;
        int am = m;
        if (MAPIN) { int tt = m / PPF; am = tt * TPF + 2 + (m - tt * PPF); }
        asrc[i] = A + (size_t)(v ? am : 0) * K + c4 * 4;
        aval[i] = v;
        bsrc[i] = W + (size_t)(n0 + row) * K + c4 * 4;
        soff[i] = row * LDT + c4 * 4;
    }

    auto issue = [&](int c) {
        int s = c % STG;
        float* As = sm + s * (2 * 128 * LDT);
        float* Bs = As + 128 * LDT;
        int kb = c * BK;
#pragma unroll
        for (int i = 0; i < 4; i++) {
            cpa16(smem_u32(As + soff[i]), asrc[i] + kb, aval[i]);
            cpa16(smem_u32(Bs + soff[i]), bsrc[i] + kb, true);
        }
    };

    float acc[4][4][4];
#pragma unroll
    for (int a = 0; a < 4; a++)
#pragma unroll
        for (int b = 0; b < 4; b++)
#pragma unroll
            for (int c = 0; c < 4; c++) acc[a][b][c] = 0.f;

    const int NC = K / BK;
    issue(0); cpa_commit();
    issue(1); cpa_commit();

    for (int c = 0; c < NC; c++) {
        cpa_wait<1>();
        __syncthreads();
        if (c + 2 < NC) issue(c + 2);
        cpa_commit();

        const float* As = sm + (c % STG) * (2 * 128 * LDT);
        const float* Bs = As + 128 * LDT;
#pragma unroll
        for (int ks = 0; ks < 4; ks++) {
            int kb = ks * 8;
            uint32_t af[4][4];
#pragma unroll
            for (int mt = 0; mt < 4; mt++) {
                const float* p = As + (wm + mt * 16 + g) * LDT + kb + t;
                af[mt][0] = fu(p[0]);
                af[mt][1] = fu(p[8 * LDT]);
                af[mt][2] = fu(p[4]);
                af[mt][3] = fu(p[8 * LDT + 4]);
            }
#pragma unroll
            for (int nt = 0; nt < 4; nt++) {
                const float* q = Bs + (wn + nt * 8 + g) * LDT + kb + t;
                uint32_t b0 = fu(q[0]), b1 = fu(q[4]);
#pragma unroll
                for (int mt = 0; mt < 4; mt++) mma8(acc[mt][nt], af[mt], b0, b1);
            }
        }
    }

    // epilogue
#pragma unroll
    for (int mt = 0; mt < 4; mt++) {
#pragma unroll
        for (int r = 0; r < 2; r++) {
            int m = m0 + wm + mt * 16 + g + r * 8;
            if (m >= M) continue;
            int dstrow = m;
            int tfrm = 0;
            if (FE) { tfrm = m / PPF; dstrow = tfrm * TPF + 2 + (m - tfrm * PPF); }
#pragma unroll
            for (int nt = 0; nt < 4; nt++) {
                int n = n0 + wn + nt * 8 + t * 2;
                float v0 = acc[mt][nt][r * 2 + 0] + bias[n];
                float v1 = acc[mt][nt][r * 2 + 1] + bias[n + 1];
                if (ACT == 1) {
                    v0 = 0.5f * v0 * (1.f + erff(v0 * 0.70710678118654752f));
                    v1 = 0.5f * v1 * (1.f + erff(v1 * 0.70710678118654752f));
                }
                if (FE) { v0 += fe[tfrm * DMODEL + n]; v1 += fe[tfrm * DMODEL + n + 1]; }
                if (RESID) {
                    const float* rr = resid + (size_t)m * N + n;
                    v0 += rr[0]; v1 += rr[1];
                }
                if (ROUND) { v0 = f2tff(v0); v1 = f2tff(v1); }
                *reinterpret_cast<float2*>(C + (size_t)dstrow * N + n) = make_float2(v0, v1);
            }
        }
    }
}

// =====================================================================
// TF32 flash attention, frame block-causal, cp.async 3-stage KV pipe.
// Block: 128 queries x 1 head, 256 threads (8 warps x 16 q-rows).
// qkv must be pre-rounded tf32. Scale (1/8) applied post-MMA (exact).
// =====================================================================
#define QLD  68
#define KLD  68
#define VLD  72
#define ASTG 3
#define ATTN_SMEM ((128*QLD + 128*QLD + ASTG*64*KLD + ASTG*64*VLD) * 4)  // 177152

__global__ __launch_bounds__(256)
void attn_tc(const float* __restrict__ qkv, float* __restrict__ ctx)
{
    extern __shared__ float sm[];
    float* Qs = sm;                        // [128][QLD]
    float* Ps = Qs + 128 * QLD;            // [128][QLD]
    float* Ks = Ps + 128 * QLD;            // [ASTG][64][KLD]
    float* Vs = Ks + ASTG * 64 * KLD;      // [ASTG][64][VLD]

    const int q0 = (gridDim.x - 1 - blockIdx.x) * 128;   // heavy tiles first
    const int h  = blockIdx.y;
    const int tid = threadIdx.x, lane = tid & 31, warp = tid >> 5;
    const int g = lane >> 2, t = lane & 3;
    const int wq = warp * 16;

    // issue Q load (async, part of group 0)
#pragma unroll
    for (int i = 0; i < 8; i++) {
        int id = tid + i * 256; int row = id >> 4; int c4 = id & 15;
        int q = q0 + row;
        cpa16(smem_u32(Qs + row * QLD + c4 * 4),
              qkv + (size_t)(q < SEQ ? q : 0) * 2304 + h * 64 + c4 * 4, q < SEQ);
    }

    auto issueKV = [&](int tIdx) {
        int s = tIdx % ASTG; int k0 = tIdx * 64;
        float* Ksb = Ks + s * 64 * KLD;
        float* Vsb = Vs + s * 64 * VLD;
#pragma unroll
        for (int i = 0; i < 4; i++) {
            int id = tid + i * 256; int row = id >> 4; int c4 = id & 15;
            int k = k0 + row;
            bool v = k < SEQ;
            const float* base = qkv + (size_t)(v ? k : 0) * 2304 + h * 64 + c4 * 4;
            cpa16(smem_u32(Ksb + row * KLD + c4 * 4), base + 768,  v);
            cpa16(smem_u32(Vsb + row * VLD + c4 * 4), base + 1536, v);
        }
    };

    int qmax = min(q0 + 127, SEQ - 1);
    int kv_end = min(SEQ, (qmax / TPF + 1) * TPF);
    const int T = (kv_end + 63) / 64;

    issueKV(0); cpa_commit();
    issueKV(1); cpa_commit();

    float o[8][4];
#pragma unroll
    for (int a = 0; a < 8; a++)
#pragma unroll
        for (int b = 0; b < 4; b++) o[a][b] = 0.f;
    float mrow[2] = {-1e30f, -1e30f}, lrow[2] = {0.f, 0.f};

    int qrow0 = q0 + wq + g;
    int qlim0 = (qrow0 / TPF + 1) * TPF;
    int qlim1 = ((qrow0 + 8) / TPF + 1) * TPF;
    int qlim_w = ((q0 + wq) / TPF + 1) * TPF;

    for (int ti = 0; ti < T; ti++) {
        cpa_wait<1>();
        __syncthreads();
        if (ti + 2 < T) issueKV(ti + 2);
        cpa_commit();

        const float* Ksb = Ks + (ti % ASTG) * 64 * KLD;
        const float* Vsb = Vs + (ti % ASTG) * 64 * VLD;
        const int k0 = ti * 64;

        // S = Q @ K^T
        float sacc[8][4];
#pragma unroll
        for (int a = 0; a < 8; a++)
#pragma unroll
            for (int b = 0; b < 4; b++) sacc[a][b] = 0.f;

#pragma unroll
        for (int ks = 0; ks < 8; ks++) {
            int kb = ks * 8;
            uint32_t af[4];
            const float* p = Qs + (wq + g) * QLD + kb + t;
            af[0] = fu(p[0]); af[1] = fu(p[8 * QLD]);
            af[2] = fu(p[4]); af[3] = fu(p[8 * QLD + 4]);
#pragma unroll
            for (int nt = 0; nt < 8; nt++) {
                const float* q = Ksb + (nt * 8 + g) * KLD + kb + t;
                mma8(sacc[nt], af, fu(q[0]), fu(q[4]));
            }
        }

        // scale
#pragma unroll
        for (int a = 0; a < 8; a++)
#pragma unroll
            for (int b = 0; b < 4; b++) sacc[a][b] *= 0.125f;

        // frame-causal mask (boundary tiles only)
        if (k0 + 63 >= qlim_w) {
#pragma unroll
            for (int nt = 0; nt < 8; nt++) {
                int kc = k0 + nt * 8 + t * 2;
                if (kc     >= qlim0) sacc[nt][0] = -1e30f;
                if (kc + 1 >= qlim0) sacc[nt][1] = -1e30f;
                if (kc     >= qlim1) sacc[nt][2] = -1e30f;
                if (kc + 1 >= qlim1) sacc[nt][3] = -1e30f;
            }
        }

        // online softmax (rows g, g+8 of this warp's 16)
#pragma unroll
        for (int r = 0; r < 2; r++) {
            float mx = -1e30f;
#pragma unroll
            for (int nt = 0; nt < 8; nt++)
                mx = fmaxf(mx, fmaxf(sacc[nt][r * 2], sacc[nt][r * 2 + 1]));
            mx = fmaxf(mx, __shfl_xor_sync(0xffffffffu, mx, 1));
            mx = fmaxf(mx, __shfl_xor_sync(0xffffffffu, mx, 2));
            float mnew = fmaxf(mrow[r], mx);
            float scl = __expf(mrow[r] - mnew);
            mrow[r] = mnew;
            float rs = 0.f;
#pragma unroll
            for (int nt = 0; nt < 8; nt++) {
                float p0 = __expf(sacc[nt][r * 2]     - mnew);
                float p1 = __expf(sacc[nt][r * 2 + 1] - mnew);
                sacc[nt][r * 2] = p0; sacc[nt][r * 2 + 1] = p1;
                rs += p0 + p1;
            }
            rs += __shfl_xor_sync(0xffffffffu, rs, 1);
            rs += __shfl_xor_sync(0xffffffffu, rs, 2);
            lrow[r] = lrow[r] * scl + rs;
#pragma unroll
            for (int nt = 0; nt < 8; nt++) { o[nt][r * 2] *= scl; o[nt][r * 2 + 1] *= scl; }
#pragma unroll
            for (int nt = 0; nt < 8; nt++) {
                float* dst = Ps + (wq + g + r * 8) * QLD + nt * 8 + t * 2;
                dst[0] = f2tff(sacc[nt][r * 2]);
                dst[1] = f2tff(sacc[nt][r * 2 + 1]);
            }
        }
        __syncwarp();

        // O += P @ V
#pragma unroll
        for (int ks = 0; ks < 8; ks++) {
            int kb = ks * 8;
            uint32_t af[4];
            const float* p = Ps + (wq + g) * QLD + kb + t;
            af[0] = fu(p[0]); af[1] = fu(p[8 * QLD]);
            af[2] = fu(p[4]); af[3] = fu(p[8 * QLD + 4]);
#pragma unroll
            for (int nt = 0; nt < 8; nt++) {
                const float* q = Vsb + (kb + t) * VLD + nt * 8 + g;
                mma8(o[nt], af, fu(q[0]), fu(q[4 * VLD]));
            }
        }
    }

    // write ctx (tf32-rounded: feeds next GEMM's A operand)
#pragma unroll
    for (int r = 0; r < 2; r++) {
        int qq = q0 + wq + g + r * 8;
        if (qq >= SEQ) continue;
        float inv = 1.f / lrow[r];
#pragma unroll
        for (int nt = 0; nt < 8; nt++) {
            float* dst = ctx + (size_t)qq * DMODEL + h * 64 + nt * 8 + t * 2;
            dst[0] = f2tff(o[nt][r * 2] * inv);
            dst[1] = f2tff(o[nt][r * 2 + 1] * inv);
        }
    }
}

// =====================================================================
// LayerNorm (vectorized, 192 threads = 1 float4/thread), tf32 output.
// =====================================================================
__device__ __forceinline__ float block_reduce6(float v)
{
    __shared__ float red[8];
    int lane = threadIdx.x & 31, w = threadIdx.x >> 5;
#pragma unroll
    for (int o = 16; o; o >>= 1) v += __shfl_xor_sync(0xffffffffu, v, o);
    if (!lane) red[w] = v;
    __syncthreads();
    if (threadIdx.x < 32) {
        v = (lane < 6) ? red[lane] : 0.f;
#pragma unroll
        for (int o = 4; o; o >>= 1) v += __shfl_xor_sync(0xffffffffu, v, o);
        if (!lane) red[0] = v;
    }
    __syncthreads();
    float r = red[0];
    __syncthreads();
    return r;
}

__global__ __launch_bounds__(192)
void ln_kernel(const float* __restrict__ x, const float* __restrict__ g,
               const float* __restrict__ b, float* __restrict__ y)
{
    const int row = blockIdx.x;
    float4 v = reinterpret_cast<const float4*>(x + (size_t)row * DMODEL)[threadIdx.x];
    float s = v.x + v.y + v.z + v.w;
    float mu = block_reduce6(s) * (1.f / DMODEL);
    float dx = v.x - mu, dy = v.y - mu, dz = v.z - mu, dw = v.w - mu;
    float var = block_reduce6(dx*dx + dy*dy + dz*dz + dw*dw) * (1.f / DMODEL);
    float rstd = rsqrtf(var + 1e-5f);
    float4 gg = reinterpret_cast<const float4*>(g)[threadIdx.x];
    float4 bb = reinterpret_cast<const float4*>(b)[threadIdx.x];
    float4 out;
    out.x = f2tff(dx * rstd * gg.x + bb.x);
    out.y = f2tff(dy * rstd * gg.y + bb.y);
    out.z = f2tff(dz * rstd * gg.z + bb.z);
    out.w = f2tff(dw * rstd * gg.w + bb.w);
    reinterpret_cast<float4*>(y + (size_t)row * DMODEL)[threadIdx.x] = out;
}

// =====================================================================
// action/state embed + RoPE
// =====================================================================
__global__ void act_state_embed(const float* __restrict__ actions,
                                const float* __restrict__ states,
                                const float* __restrict__ aw, const float* __restrict__ ab,
                                const float* __restrict__ sw, const float* __restrict__ sb,
                                float* __restrict__ x)
{
    int t = blockIdx.x >> 1;
    int which = blockIdx.x & 1;
    const float* inp = (which ? states : actions) + t * 7;
    const float* w   = which ? sw : aw;
    const float* bbv = which ? sb : ab;

    int f  = threadIdx.x;
    int de = 2 * f, dd = 2 * f + 1;
    float e = bbv[de], o = bbv[dd];
#pragma unroll
    for (int a = 0; a < 7; a++) {
        e = fmaf(inp[a], w[de * 7 + a], e);
        o = fmaf(inp[a], w[dd * 7 + a], o);
    }
    float ang = (float)t * expf(-logf(10000.f) * ((float)de / (float)DMODEL));
    float c = cosf(ang), sn = sinf(ang);
    int s = t * TPF + which;
    x[(size_t)s * DMODEL + de] = e * c - o * sn;
    x[(size_t)s * DMODEL + dd] = e * sn + o * c;
}

// =====================================================================
// host launcher
// =====================================================================
static inline void round_pass(const float* in, float* out, size_t n)
{
    int n4 = (int)(n / 4);
    round_tf32_k<<<(n4 + 255) / 256, 256>>>(in, out, n4);
}

extern "C" void kernel_launch(void* const* d_in, const int* in_sizes, int n_in,
                              void* d_out, int out_size)
{
    const float* visual_tokens  = (const float*)d_in[0];
    const float* actions        = (const float*)d_in[1];
    const float* states         = (const float*)d_in[2];
    const float* visual_proj_w  = (const float*)d_in[3];
    const float* visual_proj_b  = (const float*)d_in[4];
    const float* action_proj_w  = (const float*)d_in[5];
    const float* action_proj_b  = (const float*)d_in[6];
    const float* state_proj_w   = (const float*)d_in[7];
    const float* state_proj_b   = (const float*)d_in[8];
    const float* frame_embed    = (const float*)d_in[9];
    const float* qkv_w          = (const float*)d_in[10];
    const float* qkv_b          = (const float*)d_in[11];
    const float* attn_out_w     = (const float*)d_in[12];
    const float* attn_out_b     = (const float*)d_in[13];
    const float* ln1_g          = (const float*)d_in[14];
    const float* ln1_b          = (const float*)d_in[15];
    const float* ff1_w          = (const float*)d_in[16];
    const float* ff1_b          = (const float*)d_in[17];
    const float* ff2_w          = (const float*)d_in[18];
    const float* ff2_b          = (const float*)d_in[19];
    const float* ln2_g          = (const float*)d_in[20];
    const float* ln2_b          = (const float*)d_in[21];
    const float* out_norm_g     = (const float*)d_in[22];
    const float* out_norm_b     = (const float*)d_in[23];
    const float* output_proj_w  = (const float*)d_in[24];
    const float* output_proj_b  = (const float*)d_in[25];

    float *x, *h, *qkvb, *ctx, *ff;
    float *vt, *wvp, *wqkv, *wao, *wff1, *wff2, *wop;
    cudaGetSymbolAddress((void**)&x,    g_x);
    cudaGetSymbolAddress((void**)&h,    g_h);
    cudaGetSymbolAddress((void**)&qkvb, g_qkv);
    cudaGetSymbolAddress((void**)&ctx,  g_ctx);
    cudaGetSymbolAddress((void**)&ff,   g_ff);
    cudaGetSymbolAddress((void**)&vt,   g_vt);
    cudaGetSymbolAddress((void**)&wvp,  g_wvp);
    cudaGetSymbolAddress((void**)&wqkv, g_wqkv);
    cudaGetSymbolAddress((void**)&wao,  g_wao);
    cudaGetSymbolAddress((void**)&wff1, g_wff1);
    cudaGetSymbolAddress((void**)&wff2, g_wff2);
    cudaGetSymbolAddress((void**)&wop,  g_wop);

    cudaFuncSetAttribute(gemm_tc<0,false,false,true ,false>, cudaFuncAttributeMaxDynamicSharedMemorySize, GEMM_SMEM);
    cudaFuncSetAttribute(gemm_tc<0,false,false,false,true >, cudaFuncAttributeMaxDynamicSharedMemorySize, GEMM_SMEM);
    cudaFuncSetAttribute(gemm_tc<0,true ,false,false,false>, cudaFuncAttributeMaxDynamicSharedMemorySize, GEMM_SMEM);
    cudaFuncSetAttribute(gemm_tc<1,false,false,false,true >, cudaFuncAttributeMaxDynamicSharedMemorySize, GEMM_SMEM);
    cudaFuncSetAttribute(gemm_tc<0,false,true ,false,false>, cudaFuncAttributeMaxDynamicSharedMemorySize, GEMM_SMEM);
    cudaFuncSetAttribute(attn_tc, cudaFuncAttributeMaxDynamicSharedMemorySize, ATTN_SMEM);

    // ---- tf32 rounding prepass ----
    round_pass(visual_tokens, vt,   (size_t)VISROWS * VD);
    round_pass(visual_proj_w, wvp,  (size_t)DMODEL * VD);
    round_pass(qkv_w,         wqkv, (size_t)NL * 3 * DMODEL * DMODEL);
    round_pass(attn_out_w,    wao,  (size_t)NL * DMODEL * DMODEL);
    round_pass(ff1_w,         wff1, (size_t)NL * FF * DMODEL);
    round_pass(ff2_w,         wff2, (size_t)NL * DMODEL * FF);
    round_pass(output_proj_w, wop,  (size_t)VD * DMODEL);

    const int MT  = (SEQ + 127) / 128;   // 37
    const int MTV = VISROWS / 128;       // 36

    // ---- embeddings (visual proj fused with frame-embed add + scatter) ----
    gemm_tc<0,false,false,true,false><<<dim3(DMODEL/128, MTV), 256, GEMM_SMEM>>>(
        vt, wvp, visual_proj_b, nullptr, frame_embed, x, VISROWS, DMODEL, VD);
    act_state_embed<<<2*TT, 384>>>(actions, states,
        action_proj_w, action_proj_b, state_proj_w, state_proj_b, x);

    // ---- transformer layers ----
    for (int i = 0; i < NL; i++) {
        ln_kernel<<<SEQ, 192>>>(x, ln1_g + i*DMODEL, ln1_b + i*DMODEL, h);
        gemm_tc<0,false,false,false,true><<<dim3(3*DMODEL/128, MT), 256, GEMM_SMEM>>>(
            h, wqkv + (size_t)i*3*DMODEL*DMODEL, qkv_b + (size_t)i*3*DMODEL,
            nullptr, nullptr, qkvb, SEQ, 3*DMODEL, DMODEL);
        attn_tc<<<dim3(MT, NH), 256, ATTN_SMEM>>>(qkvb, ctx);
        gemm_tc<0,true,false,false,false><<<dim3(DMODEL/128, MT), 256, GEMM_SMEM>>>(
            ctx, wao + (size_t)i*DMODEL*DMODEL, attn_out_b + (size_t)i*DMODEL,
            x, nullptr, x, SEQ, DMODEL, DMODEL);
        ln_kernel<<<SEQ, 192>>>(x, ln2_g + i*DMODEL, ln2_b + i*DMODEL, h);
        gemm_tc<1,false,false,false,true><<<dim3(FF/128, MT), 256, GEMM_SMEM>>>(
            h, wff1 + (size_t)i*FF*DMODEL, ff1_b + (size_t)i*FF,
            nullptr, nullptr, ff, SEQ, FF, DMODEL);
        gemm_tc<0,true,false,false,false><<<dim3(DMODEL/128, MT), 256, GEMM_SMEM>>>(
            ff, wff2 + (size_t)i*DMODEL*FF, ff2_b + (size_t)i*DMODEL,
            x, nullptr, x, SEQ, DMODEL, FF);
    }

    // ---- output head ----
    ln_kernel<<<SEQ, 192>>>(x, out_norm_g, out_norm_b, h);
    gemm_tc<0,false,true,false,false><<<dim3(VD/128, MTV), 256, GEMM_SMEM>>>(
        h, wop, output_proj_b, nullptr, nullptr, (float*)d_out,
        VISROWS, VD, DMODEL);
}

// round 5
// speedup vs baseline: 6.8279x; 1.7444x over previous
#include <cuda_runtime.h>
#include <cuda_fp16.h>
#include <math.h>
#include <stdint.h>

// ---------------- problem constants ----------------
#define TT      8
#define PPF     576
#define TPF     578
#define SEQ     (TT*TPF)   // 4624
#define DMODEL  768
#define VD      1024
#define NL      12
#define NH      12
#define FF      3072
#define VISROWS (TT*PPF)   // 4608

// ---------------- scratch ----------------
__device__ float  g_x  [SEQ * DMODEL];          // fp32 residual stream
__device__ __half g_h  [SEQ * DMODEL];
__device__ __half g_qkv[SEQ * 3 * DMODEL];
__device__ __half g_ctx[SEQ * DMODEL];
__device__ __half g_ff [SEQ * FF];
// fp16 copies of inputs/weights
__device__ __half g_vt  [VISROWS * VD];
__device__ __half g_wvp [DMODEL * VD];
__device__ __half g_wqkv[NL * 3 * DMODEL * DMODEL];
__device__ __half g_wao [NL * DMODEL * DMODEL];
__device__ __half g_wff1[NL * FF * DMODEL];
__device__ __half g_wff2[NL * DMODEL * FF];
__device__ __half g_wop [VD * DMODEL];

// ---------------- helpers ----------------
__device__ __forceinline__ uint32_t smem_u32(const void* p) {
    return (uint32_t)__cvta_generic_to_shared(p);
}
__device__ __forceinline__ void cpa16(uint32_t dst, const void* src, bool v) {
    asm volatile("cp.async.cg.shared.global [%0], [%1], 16, %2;"
                 :: "r"(dst), "l"(src), "r"(v ? 16u : 0u));
}
__device__ __forceinline__ void cpa_commit() { asm volatile("cp.async.commit_group;"); }
template<int N> __device__ __forceinline__ void cpa_wait() {
    asm volatile("cp.async.wait_group %0;" :: "n"(N));
}

__device__ __forceinline__ void mma16816(float* d, const uint32_t* a, uint32_t b0, uint32_t b1) {
    asm volatile(
        "mma.sync.aligned.m16n8k16.row.col.f32.f16.f16.f32 "
        "{%0,%1,%2,%3},{%4,%5,%6,%7},{%8,%9},{%0,%1,%2,%3};"
        : "+f"(d[0]), "+f"(d[1]), "+f"(d[2]), "+f"(d[3])
        : "r"(a[0]), "r"(a[1]), "r"(a[2]), "r"(a[3]), "r"(b0), "r"(b1));
}
__device__ __forceinline__ void ldsm4(uint32_t* r, uint32_t a) {
    asm volatile("ldmatrix.sync.aligned.m8n8.x4.shared.b16 {%0,%1,%2,%3}, [%4];"
                 : "=r"(r[0]), "=r"(r[1]), "=r"(r[2]), "=r"(r[3]) : "r"(a));
}
__device__ __forceinline__ void ldsm4t(uint32_t* r, uint32_t a) {
    asm volatile("ldmatrix.sync.aligned.m8n8.x4.trans.shared.b16 {%0,%1,%2,%3}, [%4];"
                 : "=r"(r[0]), "=r"(r[1]), "=r"(r[2]), "=r"(r[3]) : "r"(a));
}
__device__ __forceinline__ uint32_t packh2(float lo, float hi) {
    __half2 h = __floats2half2_rn(lo, hi);
    return *reinterpret_cast<uint32_t*>(&h);
}

// ---------------- fp32 -> fp16 prepass ----------------
__global__ void f2h_k(const float4* __restrict__ in, uint2* __restrict__ out, int n4)
{
    int i = blockIdx.x * blockDim.x + threadIdx.x;
    if (i < n4) {
        float4 v = in[i];
        uint2 o;
        o.x = packh2(v.x, v.y);
        o.y = packh2(v.z, v.w);
        out[i] = o;
    }
}

// =====================================================================
// fp16 tensor-core GEMM: C[M,N] = act(A[M,K] @ W[N,K]^T + bias) (+resid)
// BM=128, BN=256, BK=32 halves. 8 warps (2m x 4n), warp tile 64x64.
// cp.async 3-stage; smem rows padded to 80B (conflict-free ldmatrix).
// =====================================================================
#define LDHB  80                       // smem row stride bytes (40 halves)
#define A_ST  (128 * LDHB)             // 10240 B
#define B_ST  (256 * LDHB)             // 20480 B
#define GSMEM (3 * (A_ST + B_ST))      // 92160 B

template<int ACT, bool RESID, bool MAPIN, bool FE, bool OUTH>
__global__ __launch_bounds__(256, 1)
void gemm_h(const __half* __restrict__ A, const __half* __restrict__ W,
            const float* __restrict__ bias, const float* __restrict__ resid,
            const float* __restrict__ fe, void* __restrict__ Cv,
            int M, int N, int K)
{
    extern __shared__ char smc[];
    const uint32_t sb = smem_u32(smc);
    const int tid = threadIdx.x, lane = tid & 31, warp = tid >> 5;
    const int m0 = blockIdx.y * 128, n0 = blockIdx.x * 256;
    const int wm = (warp >> 2) * 64, wn = (warp & 3) * 64;
    const int g = lane >> 2, t = lane & 3;

    // cp.async assignments: A 2 chunks/thr, B 4 chunks/thr (16B each)
    const __half* asrc[2]; uint32_t adst[2]; bool aval[2];
#pragma unroll
    for (int i = 0; i < 2; i++) {
        int id = tid + i * 256; int row = id >> 2; int c4 = id & 3;
        int m = m0 + row;
        bool v = m < M;
        int am = m;
        if (MAPIN) { int tt = m / PPF; am = tt * TPF + 2 + (m - tt * PPF); }
        asrc[i] = A + (size_t)(v ? am : 0) * K + c4 * 8;
        aval[i] = v;
        adst[i] = row * LDHB + c4 * 16;
    }
    const __half* bsrc[4]; uint32_t bdst[4];
#pragma unroll
    for (int i = 0; i < 4; i++) {
        int id = tid + i * 256; int row = id >> 2; int c4 = id & 3;
        bsrc[i] = W + (size_t)(n0 + row) * K + c4 * 8;
        bdst[i] = row * LDHB + c4 * 16;
    }

    auto fill = [&](int ch) {
        int s = ch % 3; int kb = ch * 32;
#pragma unroll
        for (int i = 0; i < 2; i++) cpa16(sb + s * A_ST + adst[i], asrc[i] + kb, aval[i]);
#pragma unroll
        for (int i = 0; i < 4; i++) cpa16(sb + 3 * A_ST + s * B_ST + bdst[i], bsrc[i] + kb, true);
        cpa_commit();
    };

    // lane fragment offsets
    const uint32_t ga = ((lane & 7) + ((lane & 8) ? 8 : 0)) * LDHB + ((lane & 16) ? 16 : 0);
    const uint32_t gb = ((lane & 7) + ((lane & 16) ? 8 : 0)) * LDHB + ((lane & 8) ? 16 : 0);

    float acc[4][8][4];
#pragma unroll
    for (int a = 0; a < 4; a++)
#pragma unroll
        for (int b = 0; b < 8; b++)
#pragma unroll
            for (int c = 0; c < 4; c++) acc[a][b][c] = 0.f;

    const int NC = K / 32;
    fill(0); fill(1);

    for (int c = 0; c < NC; c++) {
        cpa_wait<1>();
        __syncthreads();
        if (c + 2 < NC) fill(c + 2);

        const uint32_t Asb = sb + (c % 3) * A_ST + wm * LDHB + ga;
        const uint32_t Bsb = sb + 3 * A_ST + (c % 3) * B_ST + wn * LDHB + gb;
#pragma unroll
        for (int ks = 0; ks < 2; ks++) {
            uint32_t af[4][4];
#pragma unroll
            for (int mt = 0; mt < 4; mt++)
                ldsm4(af[mt], Asb + mt * 16 * LDHB + ks * 32);
            uint32_t bf[8][2];
#pragma unroll
            for (int p = 0; p < 4; p++) {
                uint32_t r[4];
                ldsm4(r, Bsb + p * 16 * LDHB + ks * 32);
                bf[2*p][0] = r[0]; bf[2*p][1] = r[1];
                bf[2*p+1][0] = r[2]; bf[2*p+1][1] = r[3];
            }
#pragma unroll
            for (int mt = 0; mt < 4; mt++)
#pragma unroll
                for (int nt = 0; nt < 8; nt++)
                    mma16816(acc[mt][nt], af[mt], bf[nt][0], bf[nt][1]);
        }
    }

    // epilogue (c-frag: rows g,g+8; cols 2t,2t+1)
#pragma unroll
    for (int mt = 0; mt < 4; mt++) {
#pragma unroll
        for (int r = 0; r < 2; r++) {
            int m = m0 + wm + mt * 16 + g + r * 8;
            if (m >= M) continue;
            int dstrow = m, tfrm = 0;
            if (FE) { tfrm = m / PPF; dstrow = tfrm * TPF + 2 + (m - tfrm * PPF); }
#pragma unroll
            for (int nt = 0; nt < 8; nt++) {
                int n = n0 + wn + nt * 8 + t * 2;
                float v0 = acc[mt][nt][r * 2 + 0] + bias[n];
                float v1 = acc[mt][nt][r * 2 + 1] + bias[n + 1];
                if (ACT == 1) {
                    v0 = 0.5f * v0 * (1.f + erff(v0 * 0.70710678118654752f));
                    v1 = 0.5f * v1 * (1.f + erff(v1 * 0.70710678118654752f));
                }
                if (FE) { v0 += fe[tfrm * DMODEL + n]; v1 += fe[tfrm * DMODEL + n + 1]; }
                if (RESID) {
                    const float2 rr = *reinterpret_cast<const float2*>(resid + (size_t)m * N + n);
                    v0 += rr.x; v1 += rr.y;
                }
                if (OUTH) {
                    __half* Ch = (__half*)Cv;
                    *reinterpret_cast<uint32_t*>(Ch + (size_t)dstrow * N + n) = packh2(v0, v1);
                } else {
                    float* Cf = (float*)Cv;
                    *reinterpret_cast<float2*>(Cf + (size_t)dstrow * N + n) = make_float2(v0, v1);
                }
            }
        }
    }
}

// =====================================================================
// fp16 flash attention, frame block-causal, cp.async 3-stage KV pipe.
// Block: 128 q x 1 head, 256 threads (8 warps x 16 q). P in registers.
// =====================================================================
#define ALDB 144                           // smem row stride bytes (72 halves)
#define QSM  (128 * ALDB)                  // 18432
#define KST  (64 * ALDB)                   // 9216
#define ATTN_SMEM (QSM + 3 * KST * 2)      // 73728

__global__ __launch_bounds__(256, 1)
void attn_h(const __half* __restrict__ qkv, __half* __restrict__ ctx)
{
    extern __shared__ char smc[];
    const uint32_t sb = smem_u32(smc);
    const uint32_t Qb = sb;
    const int q0 = (gridDim.x - 1 - blockIdx.x) * 128;   // heavy tiles first
    const int h  = blockIdx.y;
    const int tid = threadIdx.x, lane = tid & 31, warp = tid >> 5;
    const int g = lane >> 2, t = lane & 3;
    const int wq = warp * 16;

    // Q load: 128 rows x 8 chunks -> 4/thread
#pragma unroll
    for (int i = 0; i < 4; i++) {
        int id = tid + i * 256; int row = id >> 3; int c4 = id & 7;
        int q = q0 + row;
        cpa16(Qb + row * ALDB + c4 * 16,
              qkv + (size_t)(q < SEQ ? q : 0) * 2304 + h * 64 + c4 * 8, q < SEQ);
    }

    auto issueKV = [&](int tIdx) {
        int s = tIdx % 3; int k0 = tIdx * 64;
        uint32_t Kb = sb + QSM + s * KST;
        uint32_t Vb = sb + QSM + 3 * KST + s * KST;
#pragma unroll
        for (int i = 0; i < 2; i++) {
            int id = tid + i * 256; int row = id >> 3; int c4 = id & 7;
            int k = k0 + row;
            bool v = k < SEQ;
            const __half* base = qkv + (size_t)(v ? k : 0) * 2304 + h * 64 + c4 * 8;
            cpa16(Kb + row * ALDB + c4 * 16, base + 768,  v);
            cpa16(Vb + row * ALDB + c4 * 16, base + 1536, v);
        }
        cpa_commit();
    };

    int qmax = min(q0 + 127, SEQ - 1);
    int kv_end = min(SEQ, (qmax / TPF + 1) * TPF);
    const int T = (kv_end + 63) / 64;

    issueKV(0);
    issueKV(1);

    float o[8][4];
#pragma unroll
    for (int a = 0; a < 8; a++)
#pragma unroll
        for (int b = 0; b < 4; b++) o[a][b] = 0.f;
    float mrow[2] = {-1e30f, -1e30f}, lrow[2] = {0.f, 0.f};

    int qrow0 = q0 + wq + g;
    int qlim0 = (qrow0 / TPF + 1) * TPF;
    int qlim1 = ((qrow0 + 8) / TPF + 1) * TPF;
    int qlim_w = ((q0 + wq) / TPF + 1) * TPF;

    // lane fragment offsets
    const uint32_t qa = ((lane & 7) + ((lane & 8) ? 8 : 0)) * ALDB + ((lane & 16) ? 16 : 0);
    const uint32_t kb = ((lane & 7) + ((lane & 16) ? 8 : 0)) * ALDB + ((lane & 8) ? 16 : 0);
    const uint32_t va = ((lane & 7) + ((lane & 8) ? 8 : 0)) * ALDB + ((lane & 16) ? 16 : 0);

    for (int ti = 0; ti < T; ti++) {
        cpa_wait<1>();
        __syncthreads();
        if (ti + 2 < T) issueKV(ti + 2);

        const uint32_t Kb0 = sb + QSM + (ti % 3) * KST;
        const uint32_t Vb0 = sb + QSM + 3 * KST + (ti % 3) * KST;
        const int k0 = ti * 64;

        // S = Q @ K^T  (m=16q, n=64 keys, k=64 d)
        float sacc[8][4];
#pragma unroll
        for (int a = 0; a < 8; a++)
#pragma unroll
            for (int b = 0; b < 4; b++) sacc[a][b] = 0.f;

#pragma unroll
        for (int kd = 0; kd < 4; kd++) {
            uint32_t af[4];
            ldsm4(af, Qb + qa + wq * ALDB + kd * 32);
            uint32_t bf[8][2];
#pragma unroll
            for (int p = 0; p < 4; p++) {
                uint32_t r[4];
                ldsm4(r, Kb0 + kb + p * 16 * ALDB + kd * 32);
                bf[2*p][0] = r[0]; bf[2*p][1] = r[1];
                bf[2*p+1][0] = r[2]; bf[2*p+1][1] = r[3];
            }
#pragma unroll
            for (int nt = 0; nt < 8; nt++)
                mma16816(sacc[nt], af, bf[nt][0], bf[nt][1]);
        }

        // scale
#pragma unroll
        for (int a = 0; a < 8; a++)
#pragma unroll
            for (int b = 0; b < 4; b++) sacc[a][b] *= 0.125f;

        // frame-causal mask (boundary tiles only)
        if (k0 + 63 >= qlim_w) {
#pragma unroll
            for (int nt = 0; nt < 8; nt++) {
                int kc = k0 + nt * 8 + t * 2;
                if (kc     >= qlim0) sacc[nt][0] = -1e30f;
                if (kc + 1 >= qlim0) sacc[nt][1] = -1e30f;
                if (kc     >= qlim1) sacc[nt][2] = -1e30f;
                if (kc + 1 >= qlim1) sacc[nt][3] = -1e30f;
            }
        }

        // online softmax (rows g, g+8)
#pragma unroll
        for (int r = 0; r < 2; r++) {
            float mx = -1e30f;
#pragma unroll
            for (int nt = 0; nt < 8; nt++)
                mx = fmaxf(mx, fmaxf(sacc[nt][r * 2], sacc[nt][r * 2 + 1]));
            mx = fmaxf(mx, __shfl_xor_sync(0xffffffffu, mx, 1));
            mx = fmaxf(mx, __shfl_xor_sync(0xffffffffu, mx, 2));
            float mnew = fmaxf(mrow[r], mx);
            float scl = __expf(mrow[r] - mnew);
            mrow[r] = mnew;
            float rs = 0.f;
#pragma unroll
            for (int nt = 0; nt < 8; nt++) {
                float p0 = __expf(sacc[nt][r * 2]     - mnew);
                float p1 = __expf(sacc[nt][r * 2 + 1] - mnew);
                sacc[nt][r * 2] = p0; sacc[nt][r * 2 + 1] = p1;
                rs += p0 + p1;
            }
            rs += __shfl_xor_sync(0xffffffffu, rs, 1);
            rs += __shfl_xor_sync(0xffffffffu, rs, 2);
            lrow[r] = lrow[r] * scl + rs;
#pragma unroll
            for (int nt = 0; nt < 8; nt++) { o[nt][r * 2] *= scl; o[nt][r * 2 + 1] *= scl; }
        }

        // O += P @ V   (P from registers: c-frag -> a-frag)
#pragma unroll
        for (int ks = 0; ks < 4; ks++) {
            uint32_t pa[4];
            pa[0] = packh2(sacc[2*ks][0],   sacc[2*ks][1]);
            pa[1] = packh2(sacc[2*ks][2],   sacc[2*ks][3]);
            pa[2] = packh2(sacc[2*ks+1][0], sacc[2*ks+1][1]);
            pa[3] = packh2(sacc[2*ks+1][2], sacc[2*ks+1][3]);
            uint32_t bf[8][2];
#pragma unroll
            for (int p = 0; p < 4; p++) {
                uint32_t r[4];
                ldsm4t(r, Vb0 + va + ks * 16 * ALDB + p * 32);
                bf[2*p][0] = r[0]; bf[2*p][1] = r[1];
                bf[2*p+1][0] = r[2]; bf[2*p+1][1] = r[3];
            }
#pragma unroll
            for (int nt = 0; nt < 8; nt++)
                mma16816(o[nt], pa, bf[nt][0], bf[nt][1]);
        }
    }

    // write ctx (fp16)
#pragma unroll
    for (int r = 0; r < 2; r++) {
        int qq = q0 + wq + g + r * 8;
        if (qq >= SEQ) continue;
        float inv = 1.f / lrow[r];
#pragma unroll
        for (int nt = 0; nt < 8; nt++) {
            __half* dst = ctx + (size_t)qq * DMODEL + h * 64 + nt * 8 + t * 2;
            *reinterpret_cast<uint32_t*>(dst) = packh2(o[nt][r * 2] * inv, o[nt][r * 2 + 1] * inv);
        }
    }
}

// =====================================================================
// LayerNorm (192 threads, float4 in, half out)
// =====================================================================
__device__ __forceinline__ float block_reduce6(float v)
{
    __shared__ float red[8];
    int lane = threadIdx.x & 31, w = threadIdx.x >> 5;
#pragma unroll
    for (int o = 16; o; o >>= 1) v += __shfl_xor_sync(0xffffffffu, v, o);
    if (!lane) red[w] = v;
    __syncthreads();
    if (threadIdx.x < 32) {
        v = (lane < 6) ? red[lane] : 0.f;
#pragma unroll
        for (int o = 4; o; o >>= 1) v += __shfl_xor_sync(0xffffffffu, v, o);
        if (!lane) red[0] = v;
    }
    __syncthreads();
    float r = red[0];
    __syncthreads();
    return r;
}

__global__ __launch_bounds__(192)
void ln_kernel(const float* __restrict__ x, const float* __restrict__ g,
               const float* __restrict__ b, __half* __restrict__ y)
{
    const int row = blockIdx.x;
    float4 v = reinterpret_cast<const float4*>(x + (size_t)row * DMODEL)[threadIdx.x];
    float s = v.x + v.y + v.z + v.w;
    float mu = block_reduce6(s) * (1.f / DMODEL);
    float dx = v.x - mu, dy = v.y - mu, dz = v.z - mu, dw = v.w - mu;
    float var = block_reduce6(dx*dx + dy*dy + dz*dz + dw*dw) * (1.f / DMODEL);
    float rstd = rsqrtf(var + 1e-5f);
    float4 gg = reinterpret_cast<const float4*>(g)[threadIdx.x];
    float4 bb = reinterpret_cast<const float4*>(b)[threadIdx.x];
    uint2 out;
    out.x = packh2(dx * rstd * gg.x + bb.x, dy * rstd * gg.y + bb.y);
    out.y = packh2(dz * rstd * gg.z + bb.z, dw * rstd * gg.w + bb.w);
    reinterpret_cast<uint2*>(y + (size_t)row * DMODEL)[threadIdx.x] = out;
}

// =====================================================================
// action/state embed + RoPE (writes fp32 x)
// =====================================================================
__global__ void act_state_embed(const float* __restrict__ actions,
                                const float* __restrict__ states,
                                const float* __restrict__ aw, const float* __restrict__ ab,
                                const float* __restrict__ sw, const float* __restrict__ sb,
                                float* __restrict__ x)
{
    int t = blockIdx.x >> 1;
    int which = blockIdx.x & 1;
    const float* inp = (which ? states : actions) + t * 7;
    const float* w   = which ? sw : aw;
    const float* bbv = which ? sb : ab;

    int f  = threadIdx.x;
    int de = 2 * f, dd = 2 * f + 1;
    float e = bbv[de], o = bbv[dd];
#pragma unroll
    for (int a = 0; a < 7; a++) {
        e = fmaf(inp[a], w[de * 7 + a], e);
        o = fmaf(inp[a], w[dd * 7 + a], o);
    }
    float ang = (float)t * expf(-logf(10000.f) * ((float)de / (float)DMODEL));
    float c = cosf(ang), sn = sinf(ang);
    int s = t * TPF + which;
    x[(size_t)s * DMODEL + de] = e * c - o * sn;
    x[(size_t)s * DMODEL + dd] = e * sn + o * c;
}

// =====================================================================
// host launcher
// =====================================================================
static inline void h_pass(const float* in, __half* out, size_t n)
{
    int n4 = (int)(n / 4);
    f2h_k<<<(n4 + 255) / 256, 256>>>((const float4*)in, (uint2*)out, n4);
}

extern "C" void kernel_launch(void* const* d_in, const int* in_sizes, int n_in,
                              void* d_out, int out_size)
{
    const float* visual_tokens  = (const float*)d_in[0];
    const float* actions        = (const float*)d_in[1];
    const float* states         = (const float*)d_in[2];
    const float* visual_proj_w  = (const float*)d_in[3];
    const float* visual_proj_b  = (const float*)d_in[4];
    const float* action_proj_w  = (const float*)d_in[5];
    const float* action_proj_b  = (const float*)d_in[6];
    const float* state_proj_w   = (const float*)d_in[7];
    const float* state_proj_b   = (const float*)d_in[8];
    const float* frame_embed    = (const float*)d_in[9];
    const float* qkv_w          = (const float*)d_in[10];
    const float* qkv_b          = (const float*)d_in[11];
    const float* attn_out_w     = (const float*)d_in[12];
    const float* attn_out_b     = (const float*)d_in[13];
    const float* ln1_g          = (const float*)d_in[14];
    const float* ln1_b          = (const float*)d_in[15];
    const float* ff1_w          = (const float*)d_in[16];
    const float* ff1_b          = (const float*)d_in[17];
    const float* ff2_w          = (const float*)d_in[18];
    const float* ff2_b          = (const float*)d_in[19];
    const float* ln2_g          = (const float*)d_in[20];
    const float* ln2_b          = (const float*)d_in[21];
    const float* out_norm_g     = (const float*)d_in[22];
    const float* out_norm_b     = (const float*)d_in[23];
    const float* output_proj_w  = (const float*)d_in[24];
    const float* output_proj_b  = (const float*)d_in[25];

    float *x;
    __half *h, *qkvb, *ctx, *ff;
    __half *vt, *wvp, *wqkv, *wao, *wff1, *wff2, *wop;
    cudaGetSymbolAddress((void**)&x,    g_x);
    cudaGetSymbolAddress((void**)&h,    g_h);
    cudaGetSymbolAddress((void**)&qkvb, g_qkv);
    cudaGetSymbolAddress((void**)&ctx,  g_ctx);
    cudaGetSymbolAddress((void**)&ff,   g_ff);
    cudaGetSymbolAddress((void**)&vt,   g_vt);
    cudaGetSymbolAddress((void**)&wvp,  g_wvp);
    cudaGetSymbolAddress((void**)&wqkv, g_wqkv);
    cudaGetSymbolAddress((void**)&wao,  g_wao);
    cudaGetSymbolAddress((void**)&wff1, g_wff1);
    cudaGetSymbolAddress((void**)&wff2, g_wff2);
    cudaGetSymbolAddress((void**)&wop,  g_wop);

    cudaFuncSetAttribute(gemm_h<0,false,false,true ,false>, cudaFuncAttributeMaxDynamicSharedMemorySize, GSMEM);
    cudaFuncSetAttribute(gemm_h<0,false,false,false,true >, cudaFuncAttributeMaxDynamicSharedMemorySize, GSMEM);
    cudaFuncSetAttribute(gemm_h<0,true ,false,false,false>, cudaFuncAttributeMaxDynamicSharedMemorySize, GSMEM);
    cudaFuncSetAttribute(gemm_h<1,false,false,false,true >, cudaFuncAttributeMaxDynamicSharedMemorySize, GSMEM);
    cudaFuncSetAttribute(gemm_h<0,false,true ,false,false>, cudaFuncAttributeMaxDynamicSharedMemorySize, GSMEM);
    cudaFuncSetAttribute(attn_h, cudaFuncAttributeMaxDynamicSharedMemorySize, ATTN_SMEM);

    // ---- fp16 conversion prepass ----
    h_pass(visual_tokens, vt,   (size_t)VISROWS * VD);
    h_pass(visual_proj_w, wvp,  (size_t)DMODEL * VD);
    h_pass(qkv_w,         wqkv, (size_t)NL * 3 * DMODEL * DMODEL);
    h_pass(attn_out_w,    wao,  (size_t)NL * DMODEL * DMODEL);
    h_pass(ff1_w,         wff1, (size_t)NL * FF * DMODEL);
    h_pass(ff2_w,         wff2, (size_t)NL * DMODEL * FF);
    h_pass(output_proj_w, wop,  (size_t)VD * DMODEL);

    const int MT  = (SEQ + 127) / 128;   // 37
    const int MTV = VISROWS / 128;       // 36

    // ---- embeddings (visual proj fused with frame-embed add + scatter) ----
    gemm_h<0,false,false,true,false><<<dim3(DMODEL/256, MTV), 256, GSMEM>>>(
        vt, wvp, visual_proj_b, nullptr, frame_embed, x, VISROWS, DMODEL, VD);
    act_state_embed<<<2*TT, 384>>>(actions, states,
        action_proj_w, action_proj_b, state_proj_w, state_proj_b, x);

    // ---- transformer layers ----
    for (int i = 0; i < NL; i++) {
        ln_kernel<<<SEQ, 192>>>(x, ln1_g + i*DMODEL, ln1_b + i*DMODEL, h);
        gemm_h<0,false,false,false,true><<<dim3(3*DMODEL/256, MT), 256, GSMEM>>>(
            h, wqkv + (size_t)i*3*DMODEL*DMODEL, qkv_b + (size_t)i*3*DMODEL,
            nullptr, nullptr, qkvb, SEQ, 3*DMODEL, DMODEL);
        attn_h<<<dim3(MT, NH), 256, ATTN_SMEM>>>(qkvb, ctx);
        gemm_h<0,true,false,false,false><<<dim3(DMODEL/256, MT), 256, GSMEM>>>(
            ctx, wao + (size_t)i*DMODEL*DMODEL, attn_out_b + (size_t)i*DMODEL,
            x, nullptr, x, SEQ, DMODEL, DMODEL);
        ln_kernel<<<SEQ, 192>>>(x, ln2_g + i*DMODEL, ln2_b + i*DMODEL, h);
        gemm_h<1,false,false,false,true><<<dim3(FF/256, MT), 256, GSMEM>>>(
            h, wff1 + (size_t)i*FF*DMODEL, ff1_b + (size_t)i*FF,
            nullptr, nullptr, ff, SEQ, FF, DMODEL);
        gemm_h<0,true,false,false,false><<<dim3(DMODEL/256, MT), 256, GSMEM>>>(
            ff, wff2 + (size_t)i*DMODEL*FF, ff2_b + (size_t)i*DMODEL,
            x, nullptr, x, SEQ, DMODEL, FF);
    }

    // ---- output head ----
    ln_kernel<<<SEQ, 192>>>(x, out_norm_g, out_norm_b, h);
    gemm_h<0,false,true,false,false><<<dim3(VD/256, MTV), 256, GSMEM>>>(
        h, wop, output_proj_b, nullptr, nullptr, (float*)d_out,
        VISROWS, VD, DMODEL);
}

// round 6
// speedup vs baseline: 7.1989x; 1.0543x over previous
#include <cuda_runtime.h>
#include <cuda_fp16.h>
#include <math.h>
#include <stdint.h>

// ---------------- problem constants ----------------
#define TT      8
#define PPF     576
#define TPF     578
#define SEQ     (TT*TPF)   // 4624
#define DMODEL  768
#define VD      1024
#define NL      12
#define NH      12
#define FF      3072
#define VISROWS (TT*PPF)   // 4608

// ---------------- scratch ----------------
__device__ float  g_x  [SEQ * DMODEL];          // fp32 residual stream
__device__ __half g_h  [SEQ * DMODEL];
__device__ __half g_qkv[SEQ * 3 * DMODEL];
__device__ __half g_ctx[SEQ * DMODEL];
__device__ __half g_ff [SEQ * FF];
// fp16 copies of inputs/weights
__device__ __half g_vt  [VISROWS * VD];
__device__ __half g_wvp [DMODEL * VD];
__device__ __half g_wqkv[NL * 3 * DMODEL * DMODEL];
__device__ __half g_wao [NL * DMODEL * DMODEL];
__device__ __half g_wff1[NL * FF * DMODEL];
__device__ __half g_wff2[NL * DMODEL * FF];
__device__ __half g_wop [VD * DMODEL];

// ---------------- helpers ----------------
__device__ __forceinline__ uint32_t smem_u32(const void* p) {
    return (uint32_t)__cvta_generic_to_shared(p);
}
__device__ __forceinline__ void cpa16(uint32_t dst, const void* src, bool v) {
    asm volatile("cp.async.cg.shared.global [%0], [%1], 16, %2;"
                 :: "r"(dst), "l"(src), "r"(v ? 16u : 0u));
}
__device__ __forceinline__ void cpa_commit() { asm volatile("cp.async.commit_group;"); }
template<int N> __device__ __forceinline__ void cpa_wait() {
    asm volatile("cp.async.wait_group %0;" :: "n"(N));
}

__device__ __forceinline__ void mma16816(float* d, const uint32_t* a, uint32_t b0, uint32_t b1) {
    asm volatile(
        "mma.sync.aligned.m16n8k16.row.col.f32.f16.f16.f32 "
        "{%0,%1,%2,%3},{%4,%5,%6,%7},{%8,%9},{%0,%1,%2,%3};"
        : "+f"(d[0]), "+f"(d[1]), "+f"(d[2]), "+f"(d[3])
        : "r"(a[0]), "r"(a[1]), "r"(a[2]), "r"(a[3]), "r"(b0), "r"(b1));
}
__device__ __forceinline__ void ldsm4(uint32_t* r, uint32_t a) {
    asm volatile("ldmatrix.sync.aligned.m8n8.x4.shared.b16 {%0,%1,%2,%3}, [%4];"
                 : "=r"(r[0]), "=r"(r[1]), "=r"(r[2]), "=r"(r[3]) : "r"(a));
}
__device__ __forceinline__ void ldsm4t(uint32_t* r, uint32_t a) {
    asm volatile("ldmatrix.sync.aligned.m8n8.x4.trans.shared.b16 {%0,%1,%2,%3}, [%4];"
                 : "=r"(r[0]), "=r"(r[1]), "=r"(r[2]), "=r"(r[3]) : "r"(a));
}
__device__ __forceinline__ uint32_t packh2(float lo, float hi) {
    __half2 h = __floats2half2_rn(lo, hi);
    return *reinterpret_cast<uint32_t*>(&h);
}

// ---------------- fp32 -> fp16 prepass ----------------
__global__ void f2h_k(const float4* __restrict__ in, uint2* __restrict__ out, int n4)
{
    int i = blockIdx.x * blockDim.x + threadIdx.x;
    if (i < n4) {
        float4 v = in[i];
        uint2 o;
        o.x = packh2(v.x, v.y);
        o.y = packh2(v.z, v.w);
        out[i] = o;
    }
}

// =====================================================================
// fp16 tensor-core GEMM: C[M,N] = act(A[M,K] @ W[N,K]^T + bias) (+resid)
// BM=128, BN=TBN (192 or 256), BK=32 halves. 8 warps (2m x 4n),
// warp tile 64 x TBN/4. cp.async 3-stage; rows padded to 80B.
// TBN=192 makes N=768 grids exactly 148 CTAs (one full wave on GB300).
// =====================================================================
#define LDHB  80                       // smem row stride bytes (40 halves)
#define A_ST  (128 * LDHB)             // 10240 B per A stage
#define GSMEM(TBN) (3 * (A_ST + (TBN) * LDHB))

template<int TBN, int ACT, bool RESID, bool MAPIN, bool FE, bool OUTH>
__global__ __launch_bounds__(256, 1)
void gemm_h(const __half* __restrict__ A, const __half* __restrict__ W,
            const float* __restrict__ bias, const float* __restrict__ resid,
            const float* __restrict__ fe, void* __restrict__ Cv,
            int M, int N, int K)
{
    constexpr int B_ST  = TBN * LDHB;        // bytes per B stage
    constexpr int WN    = TBN / 4;           // warp n-width
    constexpr int NFR   = TBN / 32;          // n-frags per warp (8 or 6)
    constexpr int NP    = TBN / 64;          // 16-row ldsm groups per warp (4 or 3)
    constexpr int BCH   = TBN / 64;          // B cp.async chunks per thread

    extern __shared__ char smc[];
    const uint32_t sb = smem_u32(smc);
    const int tid = threadIdx.x, lane = tid & 31, warp = tid >> 5;
    const int m0 = blockIdx.y * 128, n0 = blockIdx.x * TBN;
    const int wm = (warp >> 2) * 64, wn = (warp & 3) * WN;
    const int g = lane >> 2, t = lane & 3;

    // cp.async assignments: A 2 chunks/thr, B BCH chunks/thr (16B each)
    const __half* asrc[2]; uint32_t adst[2]; bool aval[2];
#pragma unroll
    for (int i = 0; i < 2; i++) {
        int id = tid + i * 256; int row = id >> 2; int c4 = id & 3;
        int m = m0 + row;
        bool v = m < M;
        int am = m;
        if (MAPIN) { int tt = m / PPF; am = tt * TPF + 2 + (m - tt * PPF); }
        asrc[i] = A + (size_t)(v ? am : 0) * K + c4 * 8;
        aval[i] = v;
        adst[i] = row * LDHB + c4 * 16;
    }
    const __half* bsrc[BCH]; uint32_t bdst[BCH];
#pragma unroll
    for (int i = 0; i < BCH; i++) {
        int id = tid + i * 256; int row = id >> 2; int c4 = id & 3;
        bsrc[i] = W + (size_t)(n0 + row) * K + c4 * 8;
        bdst[i] = row * LDHB + c4 * 16;
    }

    auto fill = [&](int ch) {
        int s = ch % 3; int kb = ch * 32;
#pragma unroll
        for (int i = 0; i < 2; i++) cpa16(sb + s * A_ST + adst[i], asrc[i] + kb, aval[i]);
#pragma unroll
        for (int i = 0; i < BCH; i++) cpa16(sb + 3 * A_ST + s * B_ST + bdst[i], bsrc[i] + kb, true);
        cpa_commit();
    };

    // lane fragment offsets
    const uint32_t ga = ((lane & 7) + ((lane & 8) ? 8 : 0)) * LDHB + ((lane & 16) ? 16 : 0);
    const uint32_t gb = ((lane & 7) + ((lane & 16) ? 8 : 0)) * LDHB + ((lane & 8) ? 16 : 0);

    float acc[4][NFR][4];
#pragma unroll
    for (int a = 0; a < 4; a++)
#pragma unroll
        for (int b = 0; b < NFR; b++)
#pragma unroll
            for (int c = 0; c < 4; c++) acc[a][b][c] = 0.f;

    const int NC = K / 32;
    fill(0); fill(1);

    for (int c = 0; c < NC; c++) {
        cpa_wait<1>();
        __syncthreads();
        if (c + 2 < NC) fill(c + 2);

        const uint32_t Asb = sb + (c % 3) * A_ST + wm * LDHB + ga;
        const uint32_t Bsb = sb + 3 * A_ST + (c % 3) * B_ST + wn * LDHB + gb;
#pragma unroll
        for (int ks = 0; ks < 2; ks++) {
            uint32_t af[4][4];
#pragma unroll
            for (int mt = 0; mt < 4; mt++)
                ldsm4(af[mt], Asb + mt * 16 * LDHB + ks * 32);
            uint32_t bf[NFR][2];
#pragma unroll
            for (int p = 0; p < NP; p++) {
                uint32_t r[4];
                ldsm4(r, Bsb + p * 16 * LDHB + ks * 32);
                bf[2*p][0] = r[0]; bf[2*p][1] = r[1];
                bf[2*p+1][0] = r[2]; bf[2*p+1][1] = r[3];
            }
#pragma unroll
            for (int mt = 0; mt < 4; mt++)
#pragma unroll
                for (int nt = 0; nt < NFR; nt++)
                    mma16816(acc[mt][nt], af[mt], bf[nt][0], bf[nt][1]);
        }
    }

    // epilogue (c-frag: rows g,g+8; cols 2t,2t+1)
#pragma unroll
    for (int mt = 0; mt < 4; mt++) {
#pragma unroll
        for (int r = 0; r < 2; r++) {
            int m = m0 + wm + mt * 16 + g + r * 8;
            if (m >= M) continue;
            int dstrow = m, tfrm = 0;
            if (FE) { tfrm = m / PPF; dstrow = tfrm * TPF + 2 + (m - tfrm * PPF); }
#pragma unroll
            for (int nt = 0; nt < NFR; nt++) {
                int n = n0 + wn + nt * 8 + t * 2;
                float v0 = acc[mt][nt][r * 2 + 0] + bias[n];
                float v1 = acc[mt][nt][r * 2 + 1] + bias[n + 1];
                if (ACT == 1) {
                    v0 = 0.5f * v0 * (1.f + erff(v0 * 0.70710678118654752f));
                    v1 = 0.5f * v1 * (1.f + erff(v1 * 0.70710678118654752f));
                }
                if (FE) { v0 += fe[tfrm * DMODEL + n]; v1 += fe[tfrm * DMODEL + n + 1]; }
                if (RESID) {
                    const float2 rr = *reinterpret_cast<const float2*>(resid + (size_t)m * N + n);
                    v0 += rr.x; v1 += rr.y;
                }
                if (OUTH) {
                    __half* Ch = (__half*)Cv;
                    *reinterpret_cast<uint32_t*>(Ch + (size_t)dstrow * N + n) = packh2(v0, v1);
                } else {
                    float* Cf = (float*)Cv;
                    *reinterpret_cast<float2*>(Cf + (size_t)dstrow * N + n) = make_float2(v0, v1);
                }
            }
        }
    }
}

// =====================================================================
// fp16 flash attention, frame block-causal, cp.async 3-stage KV pipe.
// Block: 128 q x 1 head, 256 threads (8 warps x 16 q). P in registers.
// =====================================================================
#define ALDB 144                           // smem row stride bytes (72 halves)
#define QSM  (128 * ALDB)                  // 18432
#define KST  (64 * ALDB)                   // 9216
#define ATTN_SMEM (QSM + 3 * KST * 2)      // 73728

__global__ __launch_bounds__(256, 1)
void attn_h(const __half* __restrict__ qkv, __half* __restrict__ ctx)
{
    extern __shared__ char smc[];
    const uint32_t sb = smem_u32(smc);
    const uint32_t Qb = sb;
    const int q0 = (gridDim.x - 1 - blockIdx.x) * 128;   // heavy tiles first
    const int h  = blockIdx.y;
    const int tid = threadIdx.x, lane = tid & 31, warp = tid >> 5;
    const int g = lane >> 2, t = lane & 3;
    const int wq = warp * 16;

    // Q load: 128 rows x 8 chunks -> 4/thread
#pragma unroll
    for (int i = 0; i < 4; i++) {
        int id = tid + i * 256; int row = id >> 3; int c4 = id & 7;
        int q = q0 + row;
        cpa16(Qb + row * ALDB + c4 * 16,
              qkv + (size_t)(q < SEQ ? q : 0) * 2304 + h * 64 + c4 * 8, q < SEQ);
    }

    auto issueKV = [&](int tIdx) {
        int s = tIdx % 3; int k0 = tIdx * 64;
        uint32_t Kb = sb + QSM + s * KST;
        uint32_t Vb = sb + QSM + 3 * KST + s * KST;
#pragma unroll
        for (int i = 0; i < 2; i++) {
            int id = tid + i * 256; int row = id >> 3; int c4 = id & 7;
            int k = k0 + row;
            bool v = k < SEQ;
            const __half* base = qkv + (size_t)(v ? k : 0) * 2304 + h * 64 + c4 * 8;
            cpa16(Kb + row * ALDB + c4 * 16, base + 768,  v);
            cpa16(Vb + row * ALDB + c4 * 16, base + 1536, v);
        }
        cpa_commit();
    };

    int qmax = min(q0 + 127, SEQ - 1);
    int kv_end = min(SEQ, (qmax / TPF + 1) * TPF);
    const int T = (kv_end + 63) / 64;

    issueKV(0);
    issueKV(1);

    float o[8][4];
#pragma unroll
    for (int a = 0; a < 8; a++)
#pragma unroll
        for (int b = 0; b < 4; b++) o[a][b] = 0.f;
    float mrow[2] = {-1e30f, -1e30f}, lrow[2] = {0.f, 0.f};

    int qrow0 = q0 + wq + g;
    int qlim0 = (qrow0 / TPF + 1) * TPF;
    int qlim1 = ((qrow0 + 8) / TPF + 1) * TPF;
    int qlim_w = ((q0 + wq) / TPF + 1) * TPF;

    // lane fragment offsets
    const uint32_t qa = ((lane & 7) + ((lane & 8) ? 8 : 0)) * ALDB + ((lane & 16) ? 16 : 0);
    const uint32_t kb = ((lane & 7) + ((lane & 16) ? 8 : 0)) * ALDB + ((lane & 8) ? 16 : 0);
    const uint32_t va = ((lane & 7) + ((lane & 8) ? 8 : 0)) * ALDB + ((lane & 16) ? 16 : 0);

    for (int ti = 0; ti < T; ti++) {
        cpa_wait<1>();
        __syncthreads();
        if (ti + 2 < T) issueKV(ti + 2);

        const uint32_t Kb0 = sb + QSM + (ti % 3) * KST;
        const uint32_t Vb0 = sb + QSM + 3 * KST + (ti % 3) * KST;
        const int k0 = ti * 64;

        // S = Q @ K^T  (m=16q, n=64 keys, k=64 d)
        float sacc[8][4];
#pragma unroll
        for (int a = 0; a < 8; a++)
#pragma unroll
            for (int b = 0; b < 4; b++) sacc[a][b] = 0.f;

#pragma unroll
        for (int kd = 0; kd < 4; kd++) {
            uint32_t af[4];
            ldsm4(af, Qb + qa + wq * ALDB + kd * 32);
            uint32_t bf[8][2];
#pragma unroll
            for (int p = 0; p < 4; p++) {
                uint32_t r[4];
                ldsm4(r, Kb0 + kb + p * 16 * ALDB + kd * 32);
                bf[2*p][0] = r[0]; bf[2*p][1] = r[1];
                bf[2*p+1][0] = r[2]; bf[2*p+1][1] = r[3];
            }
#pragma unroll
            for (int nt = 0; nt < 8; nt++)
                mma16816(sacc[nt], af, bf[nt][0], bf[nt][1]);
        }

        // scale
#pragma unroll
        for (int a = 0; a < 8; a++)
#pragma unroll
            for (int b = 0; b < 4; b++) sacc[a][b] *= 0.125f;

        // frame-causal mask (boundary tiles only)
        if (k0 + 63 >= qlim_w) {
#pragma unroll
            for (int nt = 0; nt < 8; nt++) {
                int kc = k0 + nt * 8 + t * 2;
                if (kc     >= qlim0) sacc[nt][0] = -1e30f;
                if (kc + 1 >= qlim0) sacc[nt][1] = -1e30f;
                if (kc     >= qlim1) sacc[nt][2] = -1e30f;
                if (kc + 1 >= qlim1) sacc[nt][3] = -1e30f;
            }
        }

        // online softmax (rows g, g+8)
#pragma unroll
        for (int r = 0; r < 2; r++) {
            float mx = -1e30f;
#pragma unroll
            for (int nt = 0; nt < 8; nt++)
                mx = fmaxf(mx, fmaxf(sacc[nt][r * 2], sacc[nt][r * 2 + 1]));
            mx = fmaxf(mx, __shfl_xor_sync(0xffffffffu, mx, 1));
            mx = fmaxf(mx, __shfl_xor_sync(0xffffffffu, mx, 2));
            float mnew = fmaxf(mrow[r], mx);
            float scl = __expf(mrow[r] - mnew);
            mrow[r] = mnew;
            float rs = 0.f;
#pragma unroll
            for (int nt = 0; nt < 8; nt++) {
                float p0 = __expf(sacc[nt][r * 2]     - mnew);
                float p1 = __expf(sacc[nt][r * 2 + 1] - mnew);
                sacc[nt][r * 2] = p0; sacc[nt][r * 2 + 1] = p1;
                rs += p0 + p1;
            }
            rs += __shfl_xor_sync(0xffffffffu, rs, 1);
            rs += __shfl_xor_sync(0xffffffffu, rs, 2);
            lrow[r] = lrow[r] * scl + rs;
#pragma unroll
            for (int nt = 0; nt < 8; nt++) { o[nt][r * 2] *= scl; o[nt][r * 2 + 1] *= scl; }
        }

        // O += P @ V   (P from registers: c-frag -> a-frag)
#pragma unroll
        for (int ks = 0; ks < 4; ks++) {
            uint32_t pa[4];
            pa[0] = packh2(sacc[2*ks][0],   sacc[2*ks][1]);
            pa[1] = packh2(sacc[2*ks][2],   sacc[2*ks][3]);
            pa[2] = packh2(sacc[2*ks+1][0], sacc[2*ks+1][1]);
            pa[3] = packh2(sacc[2*ks+1][2], sacc[2*ks+1][3]);
            uint32_t bf[8][2];
#pragma unroll
            for (int p = 0; p < 4; p++) {
                uint32_t r[4];
                ldsm4t(r, Vb0 + va + ks * 16 * ALDB + p * 32);
                bf[2*p][0] = r[0]; bf[2*p][1] = r[1];
                bf[2*p+1][0] = r[2]; bf[2*p+1][1] = r[3];
            }
#pragma unroll
            for (int nt = 0; nt < 8; nt++)
                mma16816(o[nt], pa, bf[nt][0], bf[nt][1]);
        }
    }

    // write ctx (fp16)
#pragma unroll
    for (int r = 0; r < 2; r++) {
        int qq = q0 + wq + g + r * 8;
        if (qq >= SEQ) continue;
        float inv = 1.f / lrow[r];
#pragma unroll
        for (int nt = 0; nt < 8; nt++) {
            __half* dst = ctx + (size_t)qq * DMODEL + h * 64 + nt * 8 + t * 2;
            *reinterpret_cast<uint32_t*>(dst) = packh2(o[nt][r * 2] * inv, o[nt][r * 2 + 1] * inv);
        }
    }
}

// =====================================================================
// LayerNorm (192 threads, float4 in, half out)
// =====================================================================
__device__ __forceinline__ float block_reduce6(float v)
{
    __shared__ float red[8];
    int lane = threadIdx.x & 31, w = threadIdx.x >> 5;
#pragma unroll
    for (int o = 16; o; o >>= 1) v += __shfl_xor_sync(0xffffffffu, v, o);
    if (!lane) red[w] = v;
    __syncthreads();
    if (threadIdx.x < 32) {
        v = (lane < 6) ? red[lane] : 0.f;
#pragma unroll
        for (int o = 4; o; o >>= 1) v += __shfl_xor_sync(0xffffffffu, v, o);
        if (!lane) red[0] = v;
    }
    __syncthreads();
    float r = red[0];
    __syncthreads();
    return r;
}

__global__ __launch_bounds__(192)
void ln_kernel(const float* __restrict__ x, const float* __restrict__ g,
               const float* __restrict__ b, __half* __restrict__ y)
{
    const int row = blockIdx.x;
    float4 v = reinterpret_cast<const float4*>(x + (size_t)row * DMODEL)[threadIdx.x];
    float s = v.x + v.y + v.z + v.w;
    float mu = block_reduce6(s) * (1.f / DMODEL);
    float dx = v.x - mu, dy = v.y - mu, dz = v.z - mu, dw = v.w - mu;
    float var = block_reduce6(dx*dx + dy*dy + dz*dz + dw*dw) * (1.f / DMODEL);
    float rstd = rsqrtf(var + 1e-5f);
    float4 gg = reinterpret_cast<const float4*>(g)[threadIdx.x];
    float4 bb = reinterpret_cast<const float4*>(b)[threadIdx.x];
    uint2 out;
    out.x = packh2(dx * rstd * gg.x + bb.x, dy * rstd * gg.y + bb.y);
    out.y = packh2(dz * rstd * gg.z + bb.z, dw * rstd * gg.w + bb.w);
    reinterpret_cast<uint2*>(y + (size_t)row * DMODEL)[threadIdx.x] = out;
}

// =====================================================================
// action/state embed + RoPE (writes fp32 x)
// =====================================================================
__global__ void act_state_embed(const float* __restrict__ actions,
                                const float* __restrict__ states,
                                const float* __restrict__ aw, const float* __restrict__ ab,
                                const float* __restrict__ sw, const float* __restrict__ sb,
                                float* __restrict__ x)
{
    int t = blockIdx.x >> 1;
    int which = blockIdx.x & 1;
    const float* inp = (which ? states : actions) + t * 7;
    const float* w   = which ? sw : aw;
    const float* bbv = which ? sb : ab;

    int f  = threadIdx.x;
    int de = 2 * f, dd = 2 * f + 1;
    float e = bbv[de], o = bbv[dd];
#pragma unroll
    for (int a = 0; a < 7; a++) {
        e = fmaf(inp[a], w[de * 7 + a], e);
        o = fmaf(inp[a], w[dd * 7 + a], o);
    }
    float ang = (float)t * expf(-logf(10000.f) * ((float)de / (float)DMODEL));
    float c = cosf(ang), sn = sinf(ang);
    int s = t * TPF + which;
    x[(size_t)s * DMODEL + de] = e * c - o * sn;
    x[(size_t)s * DMODEL + dd] = e * sn + o * c;
}

// =====================================================================
// host launcher
// =====================================================================
static inline void h_pass(const float* in, __half* out, size_t n)
{
    int n4 = (int)(n / 4);
    f2h_k<<<(n4 + 255) / 256, 256>>>((const float4*)in, (uint2*)out, n4);
}

extern "C" void kernel_launch(void* const* d_in, const int* in_sizes, int n_in,
                              void* d_out, int out_size)
{
    const float* visual_tokens  = (const float*)d_in[0];
    const float* actions        = (const float*)d_in[1];
    const float* states         = (const float*)d_in[2];
    const float* visual_proj_w  = (const float*)d_in[3];
    const float* visual_proj_b  = (const float*)d_in[4];
    const float* action_proj_w  = (const float*)d_in[5];
    const float* action_proj_b  = (const float*)d_in[6];
    const float* state_proj_w   = (const float*)d_in[7];
    const float* state_proj_b   = (const float*)d_in[8];
    const float* frame_embed    = (const float*)d_in[9];
    const float* qkv_w          = (const float*)d_in[10];
    const float* qkv_b          = (const float*)d_in[11];
    const float* attn_out_w     = (const float*)d_in[12];
    const float* attn_out_b     = (const float*)d_in[13];
    const float* ln1_g          = (const float*)d_in[14];
    const float* ln1_b          = (const float*)d_in[15];
    const float* ff1_w          = (const float*)d_in[16];
    const float* ff1_b          = (const float*)d_in[17];
    const float* ff2_w          = (const float*)d_in[18];
    const float* ff2_b          = (const float*)d_in[19];
    const float* ln2_g          = (const float*)d_in[20];
    const float* ln2_b          = (const float*)d_in[21];
    const float* out_norm_g     = (const float*)d_in[22];
    const float* out_norm_b     = (const float*)d_in[23];
    const float* output_proj_w  = (const float*)d_in[24];
    const float* output_proj_b  = (const float*)d_in[25];

    float *x;
    __half *h, *qkvb, *ctx, *ff;
    __half *vt, *wvp, *wqkv, *wao, *wff1, *wff2, *wop;
    cudaGetSymbolAddress((void**)&x,    g_x);
    cudaGetSymbolAddress((void**)&h,    g_h);
    cudaGetSymbolAddress((void**)&qkvb, g_qkv);
    cudaGetSymbolAddress((void**)&ctx,  g_ctx);
    cudaGetSymbolAddress((void**)&ff,   g_ff);
    cudaGetSymbolAddress((void**)&vt,   g_vt);
    cudaGetSymbolAddress((void**)&wvp,  g_wvp);
    cudaGetSymbolAddress((void**)&wqkv, g_wqkv);
    cudaGetSymbolAddress((void**)&wao,  g_wao);
    cudaGetSymbolAddress((void**)&wff1, g_wff1);
    cudaGetSymbolAddress((void**)&wff2, g_wff2);
    cudaGetSymbolAddress((void**)&wop,  g_wop);

    // 192-wide variants
    cudaFuncSetAttribute(gemm_h<192,0,false,false,true ,false>, cudaFuncAttributeMaxDynamicSharedMemorySize, GSMEM(192));
    cudaFuncSetAttribute(gemm_h<192,0,false,false,false,true >, cudaFuncAttributeMaxDynamicSharedMemorySize, GSMEM(192));
    cudaFuncSetAttribute(gemm_h<192,0,true ,false,false,false>, cudaFuncAttributeMaxDynamicSharedMemorySize, GSMEM(192));
    cudaFuncSetAttribute(gemm_h<192,1,false,false,false,true >, cudaFuncAttributeMaxDynamicSharedMemorySize, GSMEM(192));
    // 256-wide variant (output head only)
    cudaFuncSetAttribute(gemm_h<256,0,false,true ,false,false>, cudaFuncAttributeMaxDynamicSharedMemorySize, GSMEM(256));
    cudaFuncSetAttribute(attn_h, cudaFuncAttributeMaxDynamicSharedMemorySize, ATTN_SMEM);

    // ---- fp16 conversion prepass ----
    h_pass(visual_tokens, vt,   (size_t)VISROWS * VD);
    h_pass(visual_proj_w, wvp,  (size_t)DMODEL * VD);
    h_pass(qkv_w,         wqkv, (size_t)NL * 3 * DMODEL * DMODEL);
    h_pass(attn_out_w,    wao,  (size_t)NL * DMODEL * DMODEL);
    h_pass(ff1_w,         wff1, (size_t)NL * FF * DMODEL);
    h_pass(ff2_w,         wff2, (size_t)NL * DMODEL * FF);
    h_pass(output_proj_w, wop,  (size_t)VD * DMODEL);

    const int MT  = (SEQ + 127) / 128;   // 37
    const int MTV = VISROWS / 128;       // 36

    // ---- embeddings (visual proj fused with frame-embed add + scatter) ----
    gemm_h<192,0,false,false,true,false><<<dim3(DMODEL/192, MTV), 256, GSMEM(192)>>>(
        vt, wvp, visual_proj_b, nullptr, frame_embed, x, VISROWS, DMODEL, VD);
    act_state_embed<<<2*TT, 384>>>(actions, states,
        action_proj_w, action_proj_b, state_proj_w, state_proj_b, x);

    // ---- transformer layers ----
    for (int i = 0; i < NL; i++) {
        ln_kernel<<<SEQ, 192>>>(x, ln1_g + i*DMODEL, ln1_b + i*DMODEL, h);
        gemm_h<192,0,false,false,false,true><<<dim3(3*DMODEL/192, MT), 256, GSMEM(192)>>>(
            h, wqkv + (size_t)i*3*DMODEL*DMODEL, qkv_b + (size_t)i*3*DMODEL,
            nullptr, nullptr, qkvb, SEQ, 3*DMODEL, DMODEL);
        attn_h<<<dim3(MT, NH), 256, ATTN_SMEM>>>(qkvb, ctx);
        gemm_h<192,0,true,false,false,false><<<dim3(DMODEL/192, MT), 256, GSMEM(192)>>>(
            ctx, wao + (size_t)i*DMODEL*DMODEL, attn_out_b + (size_t)i*DMODEL,
            x, nullptr, x, SEQ, DMODEL, DMODEL);
        ln_kernel<<<SEQ, 192>>>(x, ln2_g + i*DMODEL, ln2_b + i*DMODEL, h);
        gemm_h<192,1,false,false,false,true><<<dim3(FF/192, MT), 256, GSMEM(192)>>>(
            h, wff1 + (size_t)i*FF*DMODEL, ff1_b + (size_t)i*FF,
            nullptr, nullptr, ff, SEQ, FF, DMODEL);
        gemm_h<192,0,true,false,false,false><<<dim3(DMODEL/192, MT), 256, GSMEM(192)>>>(
            ff, wff2 + (size_t)i*DMODEL*FF, ff2_b + (size_t)i*DMODEL,
            x, nullptr, x, SEQ, DMODEL, FF);
    }

    // ---- output head ----
    ln_kernel<<<SEQ, 192>>>(x, out_norm_g, out_norm_b, h);
    gemm_h<256,0,false,true,false,false><<<dim3(VD/256, MTV), 256, GSMEM(256)>>>(
        h, wop, output_proj_b, nullptr, nullptr, (float*)d_out,
        VISROWS, VD, DMODEL);
}

// round 7
// speedup vs baseline: 7.7353x; 1.0745x over previous
#include <cuda_runtime.h>
#include <cuda_fp16.h>
#include <math.h>
#include <stdint.h>

// ---------------- problem constants ----------------
#define TT      8
#define PPF     576
#define TPF     578
#define SEQ     (TT*TPF)   // 4624
#define DMODEL  768
#define VD      1024
#define NL      12
#define NH      12
#define FF      3072
#define VISROWS (TT*PPF)   // 4608

// ---------------- scratch ----------------
__device__ float  g_x  [SEQ * DMODEL];          // fp32 residual stream
__device__ __half g_h  [SEQ * DMODEL];
__device__ __half g_qkv[SEQ * 3 * DMODEL];
__device__ __half g_ctx[SEQ * DMODEL];
__device__ __half g_ff [SEQ * FF];
// fp16 copies of inputs/weights
__device__ __half g_vt  [VISROWS * VD];
__device__ __half g_wvp [DMODEL * VD];
__device__ __half g_wqkv[NL * 3 * DMODEL * DMODEL];
__device__ __half g_wao [NL * DMODEL * DMODEL];
__device__ __half g_wff1[NL * FF * DMODEL];
__device__ __half g_wff2[NL * DMODEL * FF];
__device__ __half g_wop [VD * DMODEL];

// ---------------- helpers ----------------
__device__ __forceinline__ uint32_t smem_u32(const void* p) {
    return (uint32_t)__cvta_generic_to_shared(p);
}
__device__ __forceinline__ void cpa16(uint32_t dst, const void* src, bool v) {
    asm volatile("cp.async.cg.shared.global [%0], [%1], 16, %2;"
                 :: "r"(dst), "l"(src), "r"(v ? 16u : 0u));
}
__device__ __forceinline__ void cpa_commit() { asm volatile("cp.async.commit_group;"); }
template<int N> __device__ __forceinline__ void cpa_wait() {
    asm volatile("cp.async.wait_group %0;" :: "n"(N));
}

__device__ __forceinline__ void mma16816(float* d, const uint32_t* a, uint32_t b0, uint32_t b1) {
    asm volatile(
        "mma.sync.aligned.m16n8k16.row.col.f32.f16.f16.f32 "
        "{%0,%1,%2,%3},{%4,%5,%6,%7},{%8,%9},{%0,%1,%2,%3};"
        : "+f"(d[0]), "+f"(d[1]), "+f"(d[2]), "+f"(d[3])
        : "r"(a[0]), "r"(a[1]), "r"(a[2]), "r"(a[3]), "r"(b0), "r"(b1));
}
__device__ __forceinline__ void ldsm4(uint32_t* r, uint32_t a) {
    asm volatile("ldmatrix.sync.aligned.m8n8.x4.shared.b16 {%0,%1,%2,%3}, [%4];"
                 : "=r"(r[0]), "=r"(r[1]), "=r"(r[2]), "=r"(r[3]) : "r"(a));
}
__device__ __forceinline__ void ldsm4t(uint32_t* r, uint32_t a) {
    asm volatile("ldmatrix.sync.aligned.m8n8.x4.trans.shared.b16 {%0,%1,%2,%3}, [%4];"
                 : "=r"(r[0]), "=r"(r[1]), "=r"(r[2]), "=r"(r[3]) : "r"(a));
}
__device__ __forceinline__ uint32_t packh2(float lo, float hi) {
    __half2 h = __floats2half2_rn(lo, hi);
    return *reinterpret_cast<uint32_t*>(&h);
}

// ---------------- fp32 -> fp16 prepass ----------------
__global__ void f2h_k(const float4* __restrict__ in, uint2* __restrict__ out, int n4)
{
    int i = blockIdx.x * blockDim.x + threadIdx.x;
    if (i < n4) {
        float4 v = in[i];
        uint2 o;
        o.x = packh2(v.x, v.y);
        o.y = packh2(v.z, v.w);
        out[i] = o;
    }
}

// =====================================================================
// fp16 tensor-core GEMM: C[M,N] = act(A[M,K] @ W[N,K]^T + bias) (+resid)
// BM=128, BN=TBN (192 or 256). 8 warps (2m x 4n), warp tile 64 x TBN/4.
// 6-stage ring of 32-K chunks, synced every 2 chunks (64-K groups).
// K must be a multiple of 64. Rows padded to 80B.
// =====================================================================
#define LDHB  80                       // smem row stride bytes (40 halves)
#define A_ST  (128 * LDHB)             // 10240 B per 32-K A stage
#define GSMEM(TBN) (6 * (A_ST + (TBN) * LDHB))

template<int TBN, int ACT, bool RESID, bool MAPIN, bool FE, bool OUTH>
__global__ __launch_bounds__(256, 1)
void gemm_h(const __half* __restrict__ A, const __half* __restrict__ W,
            const float* __restrict__ bias, const float* __restrict__ resid,
            const float* __restrict__ fe, void* __restrict__ Cv,
            int M, int N, int K)
{
    constexpr int B_ST  = TBN * LDHB;        // bytes per 32-K B stage
    constexpr int WN    = TBN / 4;           // warp n-width
    constexpr int NFR   = TBN / 32;          // n-frags per warp (8 or 6)
    constexpr int NP    = TBN / 64;          // 16-row ldsm groups per warp
    constexpr int BCH   = TBN / 64;          // B cp.async chunks per thread

    extern __shared__ char smc[];
    const uint32_t sb = smem_u32(smc);
    const int tid = threadIdx.x, lane = tid & 31, warp = tid >> 5;
    const int m0 = blockIdx.y * 128, n0 = blockIdx.x * TBN;
    const int wm = (warp >> 2) * 64, wn = (warp & 3) * WN;
    const int g = lane >> 2, t = lane & 3;

    // cp.async assignments: A 2 chunks/thr, B BCH chunks/thr (16B each)
    const __half* asrc[2]; uint32_t adst[2]; bool aval[2];
#pragma unroll
    for (int i = 0; i < 2; i++) {
        int id = tid + i * 256; int row = id >> 2; int c4 = id & 3;
        int m = m0 + row;
        bool v = m < M;
        int am = m;
        if (MAPIN) { int tt = m / PPF; am = tt * TPF + 2 + (m - tt * PPF); }
        asrc[i] = A + (size_t)(v ? am : 0) * K + c4 * 8;
        aval[i] = v;
        adst[i] = row * LDHB + c4 * 16;
    }
    const __half* bsrc[BCH]; uint32_t bdst[BCH];
#pragma unroll
    for (int i = 0; i < BCH; i++) {
        int id = tid + i * 256; int row = id >> 2; int c4 = id & 3;
        bsrc[i] = W + (size_t)(n0 + row) * K + c4 * 8;
        bdst[i] = row * LDHB + c4 * 16;
    }

    // fill one 64-K group = two 32-K chunks; one commit
    auto fillg = [&](int grp) {
#pragma unroll
        for (int hf = 0; hf < 2; hf++) {
            int ch = grp * 2 + hf; int s = ch % 6; int kb = ch * 32;
#pragma unroll
            for (int i = 0; i < 2; i++) cpa16(sb + s * A_ST + adst[i], asrc[i] + kb, aval[i]);
#pragma unroll
            for (int i = 0; i < BCH; i++) cpa16(sb + 6 * A_ST + s * B_ST + bdst[i], bsrc[i] + kb, true);
        }
        cpa_commit();
    };

    // lane fragment offsets
    const uint32_t ga = ((lane & 7) + ((lane & 8) ? 8 : 0)) * LDHB + ((lane & 16) ? 16 : 0);
    const uint32_t gb = ((lane & 7) + ((lane & 16) ? 8 : 0)) * LDHB + ((lane & 8) ? 16 : 0);

    float acc[4][NFR][4];
#pragma unroll
    for (int a = 0; a < 4; a++)
#pragma unroll
        for (int b = 0; b < NFR; b++)
#pragma unroll
            for (int c = 0; c < 4; c++) acc[a][b][c] = 0.f;

    const int NG = K / 64;
    fillg(0); fillg(1);

    for (int grp = 0; grp < NG; grp++) {
        cpa_wait<1>();
        __syncthreads();
        if (grp + 2 < NG) fillg(grp + 2);

#pragma unroll
        for (int hf = 0; hf < 2; hf++) {
            int ch = grp * 2 + hf; int s = ch % 6;
            const uint32_t Asb = sb + s * A_ST + wm * LDHB + ga;
            const uint32_t Bsb = sb + 6 * A_ST + s * B_ST + wn * LDHB + gb;
#pragma unroll
            for (int ks = 0; ks < 2; ks++) {
                uint32_t af[4][4];
#pragma unroll
                for (int mt = 0; mt < 4; mt++)
                    ldsm4(af[mt], Asb + mt * 16 * LDHB + ks * 32);
                uint32_t bf[NFR][2];
#pragma unroll
                for (int p = 0; p < NP; p++) {
                    uint32_t r[4];
                    ldsm4(r, Bsb + p * 16 * LDHB + ks * 32);
                    bf[2*p][0] = r[0]; bf[2*p][1] = r[1];
                    bf[2*p+1][0] = r[2]; bf[2*p+1][1] = r[3];
                }
#pragma unroll
                for (int mt = 0; mt < 4; mt++)
#pragma unroll
                    for (int nt = 0; nt < NFR; nt++)
                        mma16816(acc[mt][nt], af[mt], bf[nt][0], bf[nt][1]);
            }
        }
    }

    // epilogue (c-frag: rows g,g+8; cols 2t,2t+1)
#pragma unroll
    for (int mt = 0; mt < 4; mt++) {
#pragma unroll
        for (int r = 0; r < 2; r++) {
            int m = m0 + wm + mt * 16 + g + r * 8;
            if (m >= M) continue;
            int dstrow = m, tfrm = 0;
            if (FE) { tfrm = m / PPF; dstrow = tfrm * TPF + 2 + (m - tfrm * PPF); }
#pragma unroll
            for (int nt = 0; nt < NFR; nt++) {
                int n = n0 + wn + nt * 8 + t * 2;
                float v0 = acc[mt][nt][r * 2 + 0] + bias[n];
                float v1 = acc[mt][nt][r * 2 + 1] + bias[n + 1];
                if (ACT == 1) {
                    v0 = 0.5f * v0 * (1.f + erff(v0 * 0.70710678118654752f));
                    v1 = 0.5f * v1 * (1.f + erff(v1 * 0.70710678118654752f));
                }
                if (FE) { v0 += fe[tfrm * DMODEL + n]; v1 += fe[tfrm * DMODEL + n + 1]; }
                if (RESID) {
                    const float2 rr = *reinterpret_cast<const float2*>(resid + (size_t)m * N + n);
                    v0 += rr.x; v1 += rr.y;
                }
                if (OUTH) {
                    __half* Ch = (__half*)Cv;
                    *reinterpret_cast<uint32_t*>(Ch + (size_t)dstrow * N + n) = packh2(v0, v1);
                } else {
                    float* Cf = (float*)Cv;
                    *reinterpret_cast<float2*>(Cf + (size_t)dstrow * N + n) = make_float2(v0, v1);
                }
            }
        }
    }
}

// =====================================================================
// fp16 flash attention, frame block-causal, cp.async 3-stage KV pipe.
// Block: 128 q x 1 head, 256 threads. P in registers. 2 CTAs/SM.
// =====================================================================
#define ALDB 144                           // smem row stride bytes (72 halves)
#define QSM  (128 * ALDB)                  // 18432
#define KST  (64 * ALDB)                   // 9216
#define ATTN_SMEM (QSM + 3 * KST * 2)      // 73728

__global__ __launch_bounds__(256, 2)
void attn_h(const __half* __restrict__ qkv, __half* __restrict__ ctx)
{
    extern __shared__ char smc[];
    const uint32_t sb = smem_u32(smc);
    const uint32_t Qb = sb;
    const int q0 = (gridDim.x - 1 - blockIdx.x) * 128;   // heavy tiles first
    const int h  = blockIdx.y;
    const int tid = threadIdx.x, lane = tid & 31, warp = tid >> 5;
    const int g = lane >> 2, t = lane & 3;
    const int wq = warp * 16;

    // Q load: 128 rows x 8 chunks -> 4/thread
#pragma unroll
    for (int i = 0; i < 4; i++) {
        int id = tid + i * 256; int row = id >> 3; int c4 = id & 7;
        int q = q0 + row;
        cpa16(Qb + row * ALDB + c4 * 16,
              qkv + (size_t)(q < SEQ ? q : 0) * 2304 + h * 64 + c4 * 8, q < SEQ);
    }

    auto issueKV = [&](int tIdx) {
        int s = tIdx % 3; int k0 = tIdx * 64;
        uint32_t Kb = sb + QSM + s * KST;
        uint32_t Vb = sb + QSM + 3 * KST + s * KST;
#pragma unroll
        for (int i = 0; i < 2; i++) {
            int id = tid + i * 256; int row = id >> 3; int c4 = id & 7;
            int k = k0 + row;
            bool v = k < SEQ;
            const __half* base = qkv + (size_t)(v ? k : 0) * 2304 + h * 64 + c4 * 8;
            cpa16(Kb + row * ALDB + c4 * 16, base + 768,  v);
            cpa16(Vb + row * ALDB + c4 * 16, base + 1536, v);
        }
        cpa_commit();
    };

    int qmax = min(q0 + 127, SEQ - 1);
    int kv_end = min(SEQ, (qmax / TPF + 1) * TPF);
    const int T = (kv_end + 63) / 64;

    issueKV(0);
    issueKV(1);

    float o[8][4];
#pragma unroll
    for (int a = 0; a < 8; a++)
#pragma unroll
        for (int b = 0; b < 4; b++) o[a][b] = 0.f;
    float mrow[2] = {-1e30f, -1e30f}, lrow[2] = {0.f, 0.f};

    int qrow0 = q0 + wq + g;
    int qlim0 = (qrow0 / TPF + 1) * TPF;
    int qlim1 = ((qrow0 + 8) / TPF + 1) * TPF;
    int qlim_w = ((q0 + wq) / TPF + 1) * TPF;

    // lane fragment offsets
    const uint32_t qa = ((lane & 7) + ((lane & 8) ? 8 : 0)) * ALDB + ((lane & 16) ? 16 : 0);
    const uint32_t kb = ((lane & 7) + ((lane & 16) ? 8 : 0)) * ALDB + ((lane & 8) ? 16 : 0);
    const uint32_t va = ((lane & 7) + ((lane & 8) ? 8 : 0)) * ALDB + ((lane & 16) ? 16 : 0);

    for (int ti = 0; ti < T; ti++) {
        cpa_wait<1>();
        __syncthreads();
        if (ti + 2 < T) issueKV(ti + 2);

        const uint32_t Kb0 = sb + QSM + (ti % 3) * KST;
        const uint32_t Vb0 = sb + QSM + 3 * KST + (ti % 3) * KST;
        const int k0 = ti * 64;

        // S = Q @ K^T  (m=16q, n=64 keys, k=64 d)
        float sacc[8][4];
#pragma unroll
        for (int a = 0; a < 8; a++)
#pragma unroll
            for (int b = 0; b < 4; b++) sacc[a][b] = 0.f;

#pragma unroll
        for (int kd = 0; kd < 4; kd++) {
            uint32_t af[4];
            ldsm4(af, Qb + qa + wq * ALDB + kd * 32);
            uint32_t bf[8][2];
#pragma unroll
            for (int p = 0; p < 4; p++) {
                uint32_t r[4];
                ldsm4(r, Kb0 + kb + p * 16 * ALDB + kd * 32);
                bf[2*p][0] = r[0]; bf[2*p][1] = r[1];
                bf[2*p+1][0] = r[2]; bf[2*p+1][1] = r[3];
            }
#pragma unroll
            for (int nt = 0; nt < 8; nt++)
                mma16816(sacc[nt], af, bf[nt][0], bf[nt][1]);
        }

        // scale
#pragma unroll
        for (int a = 0; a < 8; a++)
#pragma unroll
            for (int b = 0; b < 4; b++) sacc[a][b] *= 0.125f;

        // frame-causal mask (boundary tiles only)
        if (k0 + 63 >= qlim_w) {
#pragma unroll
            for (int nt = 0; nt < 8; nt++) {
                int kc = k0 + nt * 8 + t * 2;
                if (kc     >= qlim0) sacc[nt][0] = -1e30f;
                if (kc + 1 >= qlim0) sacc[nt][1] = -1e30f;
                if (kc     >= qlim1) sacc[nt][2] = -1e30f;
                if (kc + 1 >= qlim1) sacc[nt][3] = -1e30f;
            }
        }

        // online softmax (rows g, g+8)
#pragma unroll
        for (int r = 0; r < 2; r++) {
            float mx = -1e30f;
#pragma unroll
            for (int nt = 0; nt < 8; nt++)
                mx = fmaxf(mx, fmaxf(sacc[nt][r * 2], sacc[nt][r * 2 + 1]));
            mx = fmaxf(mx, __shfl_xor_sync(0xffffffffu, mx, 1));
            mx = fmaxf(mx, __shfl_xor_sync(0xffffffffu, mx, 2));
            float mnew = fmaxf(mrow[r], mx);
            float scl = __expf(mrow[r] - mnew);
            mrow[r] = mnew;
            float rs = 0.f;
#pragma unroll
            for (int nt = 0; nt < 8; nt++) {
                float p0 = __expf(sacc[nt][r * 2]     - mnew);
                float p1 = __expf(sacc[nt][r * 2 + 1] - mnew);
                sacc[nt][r * 2] = p0; sacc[nt][r * 2 + 1] = p1;
                rs += p0 + p1;
            }
            rs += __shfl_xor_sync(0xffffffffu, rs, 1);
            rs += __shfl_xor_sync(0xffffffffu, rs, 2);
            lrow[r] = lrow[r] * scl + rs;
#pragma unroll
            for (int nt = 0; nt < 8; nt++) { o[nt][r * 2] *= scl; o[nt][r * 2 + 1] *= scl; }
        }

        // O += P @ V   (P from registers: c-frag -> a-frag)
#pragma unroll
        for (int ks = 0; ks < 4; ks++) {
            uint32_t pa[4];
            pa[0] = packh2(sacc[2*ks][0],   sacc[2*ks][1]);
            pa[1] = packh2(sacc[2*ks][2],   sacc[2*ks][3]);
            pa[2] = packh2(sacc[2*ks+1][0], sacc[2*ks+1][1]);
            pa[3] = packh2(sacc[2*ks+1][2], sacc[2*ks+1][3]);
            uint32_t bf[8][2];
#pragma unroll
            for (int p = 0; p < 4; p++) {
                uint32_t r[4];
                ldsm4t(r, Vb0 + va + ks * 16 * ALDB + p * 32);
                bf[2*p][0] = r[0]; bf[2*p][1] = r[1];
                bf[2*p+1][0] = r[2]; bf[2*p+1][1] = r[3];
            }
#pragma unroll
            for (int nt = 0; nt < 8; nt++)
                mma16816(o[nt], pa, bf[nt][0], bf[nt][1]);
        }
    }

    // write ctx (fp16)
#pragma unroll
    for (int r = 0; r < 2; r++) {
        int qq = q0 + wq + g + r * 8;
        if (qq >= SEQ) continue;
        float inv = 1.f / lrow[r];
#pragma unroll
        for (int nt = 0; nt < 8; nt++) {
            __half* dst = ctx + (size_t)qq * DMODEL + h * 64 + nt * 8 + t * 2;
            *reinterpret_cast<uint32_t*>(dst) = packh2(o[nt][r * 2] * inv, o[nt][r * 2 + 1] * inv);
        }
    }
}

// =====================================================================
// LayerNorm: warp-per-row (8 rows / 256-thread block), shfl-only.
// =====================================================================
__global__ __launch_bounds__(256)
void ln_kernel(const float* __restrict__ x, const float* __restrict__ g,
               const float* __restrict__ b, __half* __restrict__ y)
{
    const int warp = threadIdx.x >> 5, lane = threadIdx.x & 31;
    const int row = blockIdx.x * 8 + warp;
    const float4* xr = reinterpret_cast<const float4*>(x + (size_t)row * DMODEL);
    float4 v[6];
    float s = 0.f;
#pragma unroll
    for (int i = 0; i < 6; i++) {
        v[i] = xr[lane + i * 32];
        s += v[i].x + v[i].y + v[i].z + v[i].w;
    }
#pragma unroll
    for (int o = 16; o; o >>= 1) s += __shfl_xor_sync(0xffffffffu, s, o);
    float mu = s * (1.f / DMODEL);
    float vs = 0.f;
#pragma unroll
    for (int i = 0; i < 6; i++) {
        float dx = v[i].x - mu, dy = v[i].y - mu, dz = v[i].z - mu, dw = v[i].w - mu;
        vs += dx*dx + dy*dy + dz*dz + dw*dw;
    }
#pragma unroll
    for (int o = 16; o; o >>= 1) vs += __shfl_xor_sync(0xffffffffu, vs, o);
    float rstd = rsqrtf(vs * (1.f / DMODEL) + 1e-5f);
    const float4* g4 = reinterpret_cast<const float4*>(g);
    const float4* b4 = reinterpret_cast<const float4*>(b);
    uint2* y2 = reinterpret_cast<uint2*>(y + (size_t)row * DMODEL);
#pragma unroll
    for (int i = 0; i < 6; i++) {
        float4 gg = g4[lane + i * 32];
        float4 bb = b4[lane + i * 32];
        uint2 out;
        out.x = packh2((v[i].x - mu) * rstd * gg.x + bb.x, (v[i].y - mu) * rstd * gg.y + bb.y);
        out.y = packh2((v[i].z - mu) * rstd * gg.z + bb.z, (v[i].w - mu) * rstd * gg.w + bb.w);
        y2[lane + i * 32] = out;
    }
}

// =====================================================================
// action/state embed + RoPE (writes fp32 x)
// =====================================================================
__global__ void act_state_embed(const float* __restrict__ actions,
                                const float* __restrict__ states,
                                const float* __restrict__ aw, const float* __restrict__ ab,
                                const float* __restrict__ sw, const float* __restrict__ sb,
                                float* __restrict__ x)
{
    int t = blockIdx.x >> 1;
    int which = blockIdx.x & 1;
    const float* inp = (which ? states : actions) + t * 7;
    const float* w   = which ? sw : aw;
    const float* bbv = which ? sb : ab;

    int f  = threadIdx.x;
    int de = 2 * f, dd = 2 * f + 1;
    float e = bbv[de], o = bbv[dd];
#pragma unroll
    for (int a = 0; a < 7; a++) {
        e = fmaf(inp[a], w[de * 7 + a], e);
        o = fmaf(inp[a], w[dd * 7 + a], o);
    }
    float ang = (float)t * expf(-logf(10000.f) * ((float)de / (float)DMODEL));
    float c = cosf(ang), sn = sinf(ang);
    int s = t * TPF + which;
    x[(size_t)s * DMODEL + de] = e * c - o * sn;
    x[(size_t)s * DMODEL + dd] = e * sn + o * c;
}

// =====================================================================
// host launcher
// =====================================================================
static inline void h_pass(const float* in, __half* out, size_t n)
{
    int n4 = (int)(n / 4);
    f2h_k<<<(n4 + 255) / 256, 256>>>((const float4*)in, (uint2*)out, n4);
}

extern "C" void kernel_launch(void* const* d_in, const int* in_sizes, int n_in,
                              void* d_out, int out_size)
{
    const float* visual_tokens  = (const float*)d_in[0];
    const float* actions        = (const float*)d_in[1];
    const float* states         = (const float*)d_in[2];
    const float* visual_proj_w  = (const float*)d_in[3];
    const float* visual_proj_b  = (const float*)d_in[4];
    const float* action_proj_w  = (const float*)d_in[5];
    const float* action_proj_b  = (const float*)d_in[6];
    const float* state_proj_w   = (const float*)d_in[7];
    const float* state_proj_b   = (const float*)d_in[8];
    const float* frame_embed    = (const float*)d_in[9];
    const float* qkv_w          = (const float*)d_in[10];
    const float* qkv_b          = (const float*)d_in[11];
    const float* attn_out_w     = (const float*)d_in[12];
    const float* attn_out_b     = (const float*)d_in[13];
    const float* ln1_g          = (const float*)d_in[14];
    const float* ln1_b          = (const float*)d_in[15];
    const float* ff1_w          = (const float*)d_in[16];
    const float* ff1_b          = (const float*)d_in[17];
    const float* ff2_w          = (const float*)d_in[18];
    const float* ff2_b          = (const float*)d_in[19];
    const float* ln2_g          = (const float*)d_in[20];
    const float* ln2_b          = (const float*)d_in[21];
    const float* out_norm_g     = (const float*)d_in[22];
    const float* out_norm_b     = (const float*)d_in[23];
    const float* output_proj_w  = (const float*)d_in[24];
    const float* output_proj_b  = (const float*)d_in[25];

    float *x;
    __half *h, *qkvb, *ctx, *ff;
    __half *vt, *wvp, *wqkv, *wao, *wff1, *wff2, *wop;
    cudaGetSymbolAddress((void**)&x,    g_x);
    cudaGetSymbolAddress((void**)&h,    g_h);
    cudaGetSymbolAddress((void**)&qkvb, g_qkv);
    cudaGetSymbolAddress((void**)&ctx,  g_ctx);
    cudaGetSymbolAddress((void**)&ff,   g_ff);
    cudaGetSymbolAddress((void**)&vt,   g_vt);
    cudaGetSymbolAddress((void**)&wvp,  g_wvp);
    cudaGetSymbolAddress((void**)&wqkv, g_wqkv);
    cudaGetSymbolAddress((void**)&wao,  g_wao);
    cudaGetSymbolAddress((void**)&wff1, g_wff1);
    cudaGetSymbolAddress((void**)&wff2, g_wff2);
    cudaGetSymbolAddress((void**)&wop,  g_wop);

    // 192-wide variants
    cudaFuncSetAttribute(gemm_h<192,0,false,false,true ,false>, cudaFuncAttributeMaxDynamicSharedMemorySize, GSMEM(192));
    cudaFuncSetAttribute(gemm_h<192,0,false,false,false,true >, cudaFuncAttributeMaxDynamicSharedMemorySize, GSMEM(192));
    cudaFuncSetAttribute(gemm_h<192,0,true ,false,false,false>, cudaFuncAttributeMaxDynamicSharedMemorySize, GSMEM(192));
    cudaFuncSetAttribute(gemm_h<192,1,false,false,false,true >, cudaFuncAttributeMaxDynamicSharedMemorySize, GSMEM(192));
    // 256-wide variant (output head only)
    cudaFuncSetAttribute(gemm_h<256,0,false,true ,false,false>, cudaFuncAttributeMaxDynamicSharedMemorySize, GSMEM(256));
    cudaFuncSetAttribute(attn_h, cudaFuncAttributeMaxDynamicSharedMemorySize, ATTN_SMEM);

    // ---- fp16 conversion prepass ----
    h_pass(visual_tokens, vt,   (size_t)VISROWS * VD);
    h_pass(visual_proj_w, wvp,  (size_t)DMODEL * VD);
    h_pass(qkv_w,         wqkv, (size_t)NL * 3 * DMODEL * DMODEL);
    h_pass(attn_out_w,    wao,  (size_t)NL * DMODEL * DMODEL);
    h_pass(ff1_w,         wff1, (size_t)NL * FF * DMODEL);
    h_pass(ff2_w,         wff2, (size_t)NL * DMODEL * FF);
    h_pass(output_proj_w, wop,  (size_t)VD * DMODEL);

    const int MT  = (SEQ + 127) / 128;   // 37
    const int MTV = VISROWS / 128;       // 36

    // ---- embeddings (visual proj fused with frame-embed add + scatter) ----
    gemm_h<192,0,false,false,true,false><<<dim3(DMODEL/192, MTV), 256, GSMEM(192)>>>(
        vt, wvp, visual_proj_b, nullptr, frame_embed, x, VISROWS, DMODEL, VD);
    act_state_embed<<<2*TT, 384>>>(actions, states,
        action_proj_w, action_proj_b, state_proj_w, state_proj_b, x);

    // ---- transformer layers ----
    for (int i = 0; i < NL; i++) {
        ln_kernel<<<SEQ/8, 256>>>(x, ln1_g + i*DMODEL, ln1_b + i*DMODEL, h);
        gemm_h<192,0,false,false,false,true><<<dim3(3*DMODEL/192, MT), 256, GSMEM(192)>>>(
            h, wqkv + (size_t)i*3*DMODEL*DMODEL, qkv_b + (size_t)i*3*DMODEL,
            nullptr, nullptr, qkvb, SEQ, 3*DMODEL, DMODEL);
        attn_h<<<dim3(MT, NH), 256, ATTN_SMEM>>>(qkvb, ctx);
        gemm_h<192,0,true,false,false,false><<<dim3(DMODEL/192, MT), 256, GSMEM(192)>>>(
            ctx, wao + (size_t)i*DMODEL*DMODEL, attn_out_b + (size_t)i*DMODEL,
            x, nullptr, x, SEQ, DMODEL, DMODEL);
        ln_kernel<<<SEQ/8, 256>>>(x, ln2_g + i*DMODEL, ln2_b + i*DMODEL, h);
        gemm_h<192,1,false,false,false,true><<<dim3(FF/192, MT), 256, GSMEM(192)>>>(
            h, wff1 + (size_t)i*FF*DMODEL, ff1_b + (size_t)i*FF,
            nullptr, nullptr, ff, SEQ, FF, DMODEL);
        gemm_h<192,0,true,false,false,false><<<dim3(DMODEL/192, MT), 256, GSMEM(192)>>>(
            ff, wff2 + (size_t)i*DMODEL*FF, ff2_b + (size_t)i*DMODEL,
            x, nullptr, x, SEQ, DMODEL, FF);
    }

    // ---- output head ----
    ln_kernel<<<SEQ/8, 256>>>(x, out_norm_g, out_norm_b, h);
    gemm_h<256,0,false,true,false,false><<<dim3(VD/256, MTV), 256, GSMEM(256)>>>(
        h, wop, output_proj_b, nullptr, nullptr, (float*)d_out,
        VISROWS, VD, DMODEL);
}